// round 1
// baseline (speedup 1.0000x reference)
#include <cuda_runtime.h>

#define B_  4
#define T_  128
#define C_  512
#define NH_ 8
#define HS_ 64
#define BTC (B_*T_*C_)
#define SCALE_ 0.125f

// Scratch (allocation-free rule: __device__ globals)
__device__ float g_P[3 * BTC];      // p0,p1,p2 in (B,T,C) layout
__device__ float g_V[2 * BTC];      // V0,V1 in (B,T,C) layout
__device__ float g_s2[B_ * NH_ * T_];
__device__ float g_y[BTC];          // (B,T,C) layout

// ---------------------------------------------------------------------------
// Generic fp32 GEMM body: C[M,N] = A[M,K] @ B[K,N], row-major.
// Tile 64x64, BK=16, 256 threads, 4x4 per thread.
// Requires M%64==0, N%64==0, K%16==0 (true for all our shapes).
// ---------------------------------------------------------------------------
#define BMg 64
#define BNg 64
#define BKg 16

__device__ __forceinline__ void gemm_body(
    const float* __restrict__ A, const float* __restrict__ Bm,
    float* __restrict__ Cm, int M, int N, int K)
{
    __shared__ float As[BKg][BMg];
    __shared__ float Bs[BKg][BNg];

    const int tid = threadIdx.x;        // 0..255
    const int tx = tid & 15;            // col group 0..15
    const int ty = tid >> 4;            // row group 0..15
    const int row0 = blockIdx.y * BMg;
    const int col0 = blockIdx.x * BNg;

    // load mappings
    const int lr = tid >> 2;            // 0..63 (A row within tile)
    const int lk = (tid & 3) * 4;       // 0,4,8,12 (A k within tile)
    const int kr = tid >> 4;            // 0..15 (B k within tile)
    const int nc = (tid & 15) * 4;      // 0..60 (B col within tile)

    float acc[4][4];
#pragma unroll
    for (int r = 0; r < 4; r++)
#pragma unroll
        for (int c = 0; c < 4; c++) acc[r][c] = 0.f;

    for (int k0 = 0; k0 < K; k0 += BKg) {
        float4 av = *(const float4*)&A[(size_t)(row0 + lr) * K + k0 + lk];
        As[lk + 0][lr] = av.x;
        As[lk + 1][lr] = av.y;
        As[lk + 2][lr] = av.z;
        As[lk + 3][lr] = av.w;
        float4 bv = *(const float4*)&Bm[(size_t)(k0 + kr) * N + col0 + nc];
        *(float4*)&Bs[kr][nc] = bv;
        __syncthreads();

#pragma unroll
        for (int kk = 0; kk < BKg; kk++) {
            float4 a4 = *(const float4*)&As[kk][ty * 4];
            float4 b4 = *(const float4*)&Bs[kk][tx * 4];
            float ar[4] = {a4.x, a4.y, a4.z, a4.w};
            float br[4] = {b4.x, b4.y, b4.z, b4.w};
#pragma unroll
            for (int r = 0; r < 4; r++)
#pragma unroll
                for (int c = 0; c < 4; c++)
                    acc[r][c] = fmaf(ar[r], br[c], acc[r][c]);
        }
        __syncthreads();
    }

#pragma unroll
    for (int r = 0; r < 4; r++) {
        float4 out = make_float4(acc[r][0], acc[r][1], acc[r][2], acc[r][3]);
        *(float4*)&Cm[(size_t)(row0 + ty * 4 + r) * N + col0 + tx * 4] = out;
    }
}

// Fused 3-way projection: g_P[z] = x @ Wp_z, each 512x512x512. grid (8,8,3)
__global__ void proj_kernel(const float* __restrict__ x,
                            const float* __restrict__ W0,
                            const float* __restrict__ W1,
                            const float* __restrict__ W2)
{
    const int z = blockIdx.z;
    const float* W = (z == 0) ? W0 : ((z == 1) ? W1 : W2);
    gemm_body(x, W, g_P + (size_t)z * BTC, B_ * T_, C_, C_);
}

// V0 = reshape(p1,(4096,64)) @ Wv0 ; V1 = reshape(p2,...) @ Wv1. grid (1,64,2)
__global__ void vproj_kernel(const float* __restrict__ Wv0,
                             const float* __restrict__ Wv1)
{
    const int z = blockIdx.z;
    gemm_body(g_P + (size_t)(z + 1) * BTC, z ? Wv1 : Wv0,
              g_V + (size_t)z * BTC, B_ * T_ * NH_, HS_, HS_);
}

// Final: out = g_y @ Wc, 512x512x512. grid (8,8)
__global__ void out_kernel(const float* __restrict__ Wc, float* __restrict__ out)
{
    gemm_body(g_y, Wc, out, B_ * T_, C_, C_);
}

// ---------------------------------------------------------------------------
// s2[b,h,t] = sum_d p2[b,h,t,d].  One warp per (b,t,h) row of reshaped p2.
// ---------------------------------------------------------------------------
__global__ void s2_kernel()
{
    const int warp = (blockIdx.x * blockDim.x + threadIdx.x) >> 5;
    const int lane = threadIdx.x & 31;
    if (warp >= B_ * T_ * NH_) return;
    const float* row = g_P + (size_t)2 * BTC + (size_t)warp * HS_;
    float v = row[lane] + row[lane + 32];
#pragma unroll
    for (int o = 16; o; o >>= 1) v += __shfl_down_sync(0xffffffffu, v, o);
    if (lane == 0) {
        const int b = warp / (T_ * NH_);
        const int t = (warp / NH_) % T_;
        const int h = warp % NH_;
        g_s2[(b * NH_ + h) * T_ + t] = v;
    }
}

// ---------------------------------------------------------------------------
// Main higher-order attention. One block per (b,h,i), 64 threads (thread=d).
//   a[j]   = SCALE * p0[i]·p1[j],  j<=i
//   m_i    = max over k<=j<=i of a[j]*s2[k]  (prefix max/min trick, exact)
//   y[i,d] = (1/Z) sum_j V0[j,d] * sum_k exp(a[j]*s2[k]-m) * V1[k,d]
// ---------------------------------------------------------------------------
__global__ __launch_bounds__(64) void attn_kernel()
{
    const int i = T_ - 1 - blockIdx.x;   // big-i blocks first (load balance)
    const int h = blockIdx.y;
    const int b = blockIdx.z;
    const int tid = threadIdx.x;         // = d

    __shared__ float s_s2[T_];
    __shared__ float s_a[T_];
    __shared__ float s_w[2][132];        // double-buffered exp row (zero-padded)
    __shared__ float s_v1t[HS_][132];    // V1 transposed: [d][k], padded stride
    __shared__ float s_p0[HS_];
    __shared__ float s_red[64];

    const size_t headoff = (size_t)(b * T_) * C_ + (size_t)h * HS_;
    const float* p0 = g_P + headoff + (size_t)i * C_;
    const float* p1 = g_P + BTC + headoff;
    const float* v0 = g_V + headoff;
    const float* v1 = g_V + BTC + headoff;
    const float* s2r = g_s2 + (b * NH_ + h) * T_;

    // loads
    s_p0[tid] = p0[tid];
    for (int j = tid; j <= i; j += 64) s_s2[j] = s2r[j];
    for (int k = tid; k < 132; k += 64) { s_w[0][k] = 0.f; s_w[1][k] = 0.f; }
    for (int j = 0; j <= i; j++) s_v1t[tid][j] = v1[(size_t)j * C_ + tid];
    for (int j = i + 1; j <= (i | 3); j++) s_v1t[tid][j] = 0.f;  // tail guard
    __syncthreads();

    // a[j] = SCALE * p0[i] . p1[j]
    for (int j = tid; j <= i; j += 64) {
        const float* r = p1 + (size_t)j * C_;
        float dot = 0.f;
#pragma unroll
        for (int d = 0; d < HS_; d += 4) {
            float4 pv = *(const float4*)&s_p0[d];
            float4 rv = __ldg((const float4*)(r + d));
            dot = fmaf(pv.x, rv.x, dot);
            dot = fmaf(pv.y, rv.y, dot);
            dot = fmaf(pv.z, rv.z, dot);
            dot = fmaf(pv.w, rv.w, dot);
        }
        s_a[j] = dot * SCALE_;
    }
    __syncthreads();

    // exact max over valid triples via prefix max/min of s2
    if (tid == 0) {
        float pmax = -3.4e38f, pmin = 3.4e38f, m = -3.4e38f;
        for (int j = 0; j <= i; j++) {
            float s = s_s2[j];
            pmax = fmaxf(pmax, s);
            pmin = fminf(pmin, s);
            float aj = s_a[j];
            float cand = (aj >= 0.f) ? aj * pmax : aj * pmin;
            m = fmaxf(m, cand);
        }
        s_red[0] = m;
    }
    __syncthreads();
    const float negm = -s_red[0];

    float zpart = 0.f, yacc = 0.f;
    const float* v1row = &s_v1t[tid][0];

    for (int j = 0; j <= i; j++) {
        const float aj = s_a[j];
        float* wb = s_w[j & 1];
        for (int k = tid; k <= j; k += 64) {
            float w = __expf(fmaf(aj, s_s2[k], negm));
            wb[k] = w;
            zpart += w;
        }
        __syncthreads();   // one sync per j; double buffer covers next-iter writes

        float acc = 0.f;
        const int n4 = (j >> 2) + 1;                 // ceil((j+1)/4)
        const float4* w4p = (const float4*)wb;
#pragma unroll 4
        for (int q = 0; q < n4; q++) {
            float4 w4 = w4p[q];
            float4 v4 = *(const float4*)(v1row + 4 * q);
            acc = fmaf(w4.x, v4.x, acc);
            acc = fmaf(w4.y, v4.y, acc);
            acc = fmaf(w4.z, v4.z, acc);
            acc = fmaf(w4.w, v4.w, acc);
        }
        yacc = fmaf(__ldg(&v0[(size_t)j * C_ + tid]), acc, yacc);
    }

    // reduce Z across 64 threads
    __syncthreads();
    s_red[tid] = zpart;
    __syncthreads();
    if (tid < 32) {
        float v = s_red[tid] + s_red[tid + 32];
#pragma unroll
        for (int o = 16; o; o >>= 1) v += __shfl_down_sync(0xffffffffu, v, o);
        if (tid == 0) s_red[0] = v;
    }
    __syncthreads();
    const float Z = s_red[0];

    g_y[(size_t)(b * T_ + i) * C_ + (size_t)h * HS_ + tid] = yacc / Z;
}

// ---------------------------------------------------------------------------
extern "C" void kernel_launch(void* const* d_in, const int* in_sizes, int n_in,
                              void* d_out, int out_size)
{
    (void)in_sizes; (void)n_in; (void)out_size;
    const float* x   = (const float*)d_in[0];
    const float* Wp0 = (const float*)d_in[1];
    const float* Wp1 = (const float*)d_in[2];
    const float* Wp2 = (const float*)d_in[3];
    const float* Wv0 = (const float*)d_in[4];
    const float* Wv1 = (const float*)d_in[5];
    const float* Wc  = (const float*)d_in[6];
    float* out = (float*)d_out;

    proj_kernel<<<dim3(C_ / BNg, (B_ * T_) / BMg, 3), 256>>>(x, Wp0, Wp1, Wp2);
    vproj_kernel<<<dim3(1, (B_ * T_ * NH_) / BMg, 2), 256>>>(Wv0, Wv1);
    s2_kernel<<<(B_ * T_ * NH_ * 32 + 255) / 256, 256>>>();
    attn_kernel<<<dim3(T_, NH_, B_), 64>>>();
    out_kernel<<<dim3(C_ / BNg, (B_ * T_) / BMg), 256>>>(Wc, out);
}

// round 2
// speedup vs baseline: 1.4797x; 1.4797x over previous
#include <cuda_runtime.h>

#define B_  4
#define T_  128
#define C_  512
#define NH_ 8
#define HS_ 64
#define BTC (B_*T_*C_)
#define SCALE_ 0.125f
#define JB_ 8   // j rows per batch in attn kernel

// Scratch (allocation-free rule: __device__ globals)
__device__ float g_P[3 * BTC];      // p0,p1,p2 in (B,T,C) layout
__device__ float g_V[2 * BTC];      // V0,V1 in (B,T,C) layout
__device__ float g_s2[B_ * NH_ * T_];
__device__ float g_y[BTC];          // (B,T,C) layout

// ---------------------------------------------------------------------------
// Generic fp32 GEMM body: C[M,N] = A[M,K] @ B[K,N], row-major.
// Tile 64x64, BK=16, 256 threads, 4x4 per thread.
// ---------------------------------------------------------------------------
#define BMg 64
#define BNg 64
#define BKg 16

__device__ __forceinline__ void gemm_body(
    const float* __restrict__ A, const float* __restrict__ Bm,
    float* __restrict__ Cm, int M, int N, int K)
{
    __shared__ float As[BKg][BMg];
    __shared__ float Bs[BKg][BNg];

    const int tid = threadIdx.x;
    const int tx = tid & 15;
    const int ty = tid >> 4;
    const int row0 = blockIdx.y * BMg;
    const int col0 = blockIdx.x * BNg;

    const int lr = tid >> 2;
    const int lk = (tid & 3) * 4;
    const int kr = tid >> 4;
    const int nc = (tid & 15) * 4;

    float acc[4][4];
#pragma unroll
    for (int r = 0; r < 4; r++)
#pragma unroll
        for (int c = 0; c < 4; c++) acc[r][c] = 0.f;

    for (int k0 = 0; k0 < K; k0 += BKg) {
        float4 av = *(const float4*)&A[(size_t)(row0 + lr) * K + k0 + lk];
        As[lk + 0][lr] = av.x;
        As[lk + 1][lr] = av.y;
        As[lk + 2][lr] = av.z;
        As[lk + 3][lr] = av.w;
        float4 bv = *(const float4*)&Bm[(size_t)(k0 + kr) * N + col0 + nc];
        *(float4*)&Bs[kr][nc] = bv;
        __syncthreads();

#pragma unroll
        for (int kk = 0; kk < BKg; kk++) {
            float4 a4 = *(const float4*)&As[kk][ty * 4];
            float4 b4 = *(const float4*)&Bs[kk][tx * 4];
            float ar[4] = {a4.x, a4.y, a4.z, a4.w};
            float br[4] = {b4.x, b4.y, b4.z, b4.w};
#pragma unroll
            for (int r = 0; r < 4; r++)
#pragma unroll
                for (int c = 0; c < 4; c++)
                    acc[r][c] = fmaf(ar[r], br[c], acc[r][c]);
        }
        __syncthreads();
    }

#pragma unroll
    for (int r = 0; r < 4; r++) {
        float4 out = make_float4(acc[r][0], acc[r][1], acc[r][2], acc[r][3]);
        *(float4*)&Cm[(size_t)(row0 + ty * 4 + r) * N + col0 + tx * 4] = out;
    }
}

__global__ void proj_kernel(const float* __restrict__ x,
                            const float* __restrict__ W0,
                            const float* __restrict__ W1,
                            const float* __restrict__ W2)
{
    const int z = blockIdx.z;
    const float* W = (z == 0) ? W0 : ((z == 1) ? W1 : W2);
    gemm_body(x, W, g_P + (size_t)z * BTC, B_ * T_, C_, C_);
}

__global__ void vproj_kernel(const float* __restrict__ Wv0,
                             const float* __restrict__ Wv1)
{
    const int z = blockIdx.z;
    gemm_body(g_P + (size_t)(z + 1) * BTC, z ? Wv1 : Wv0,
              g_V + (size_t)z * BTC, B_ * T_ * NH_, HS_, HS_);
}

__global__ void out_kernel(const float* __restrict__ Wc, float* __restrict__ out)
{
    gemm_body(g_y, Wc, out, B_ * T_, C_, C_);
}

// ---------------------------------------------------------------------------
// s2[b,h,t] = sum_d p2[b,h,t,d]
// ---------------------------------------------------------------------------
__global__ void s2_kernel()
{
    const int warp = (blockIdx.x * blockDim.x + threadIdx.x) >> 5;
    const int lane = threadIdx.x & 31;
    if (warp >= B_ * T_ * NH_) return;
    const float* row = g_P + (size_t)2 * BTC + (size_t)warp * HS_;
    float v = row[lane] + row[lane + 32];
#pragma unroll
    for (int o = 16; o; o >>= 1) v += __shfl_down_sync(0xffffffffu, v, o);
    if (lane == 0) {
        const int b = warp / (T_ * NH_);
        const int t = (warp / NH_) % T_;
        const int h = warp % NH_;
        g_s2[(b * NH_ + h) * T_ + t] = v;
    }
}

// FMA-only exp (no MUFU): exp(x) = 2^(x*log2e), rint range reduction,
// degree-4 poly on f in [-0.5, 0.5]. rel err <= ~6e-5. x expected <= ~0.
__device__ __forceinline__ float fast_exp(float x)
{
    float t = fmaxf(x * 1.4426950408889634f, -126.0f);
    int ei = __float2int_rn(t);
    float f = t - (float)ei;
    float p = 9.618129e-3f;
    p = fmaf(p, f, 5.550411e-2f);
    p = fmaf(p, f, 2.402265e-1f);
    p = fmaf(p, f, 6.931472e-1f);
    p = fmaf(p, f, 1.0f);
    return __int_as_float(__float_as_int(p) + (ei << 23));
}

// ---------------------------------------------------------------------------
// Higher-order attention, restructured:
//   block = (b,h,i), 256 threads = (d in [0,64), q in [0,4)).
//   thread (d,q) holds V1[32q+kk][d] in 32 registers.
//   y_d = (1/Z) * sum_{j<=i} V0[j,d] * sum_{k<=j} w[j,k] * V1[k,d]
//       = (1/Z) * sum over (j,k) pairs — separable per thread over k-chunks.
//   w rows produced in 8-j batches into double-buffered smem (zero padded),
//   consumed via broadcast LDS.128. One __syncthreads per batch.
// ---------------------------------------------------------------------------
__global__ __launch_bounds__(256) void attn_kernel()
{
    const int i = T_ - 1 - blockIdx.x;   // big-i first (load balance)
    const int h = blockIdx.y;
    const int b = blockIdx.z;
    const int tid = threadIdx.x;
    const int d = tid & 63;
    const int q = tid >> 6;              // k-chunk index
    const int lane = tid & 31;
    const int warp = tid >> 5;

    __shared__ float s_w[2][JB_][128];   // w batches (zero-padded)
    __shared__ float s_v0[T_ * 64];      // V0[j][d]
    __shared__ float s_s2[T_];
    __shared__ float s_a[T_];
    __shared__ float s_p0[HS_];
    __shared__ float s_z[256];
    __shared__ float s_part[256];
    __shared__ float s_m;

    const size_t headoff = (size_t)(b * T_) * C_ + (size_t)h * HS_;
    const float* p0 = g_P + headoff + (size_t)i * C_;
    const float* p1 = g_P + BTC + headoff;
    const float* v0 = g_V + headoff;
    const float* v1 = g_V + BTC + headoff;
    const float* s2r = g_s2 + (b * NH_ + h) * T_;

    // ---- loads ----
    if (tid < 64) s_p0[tid] = p0[tid];
    if (tid < 128) s_s2[tid] = s2r[tid];
    for (int idx = tid; idx < (i + 1) * 64; idx += 256)
        s_v0[idx] = __ldg(&v0[(size_t)(idx >> 6) * C_ + (idx & 63)]);

    // V1 chunk into registers: v1r[kk] = V1[32q+kk][d]  (coalesced per warp)
    float v1r[32];
#pragma unroll
    for (int kk = 0; kk < 32; kk++)
        v1r[kk] = __ldg(&v1[(size_t)((q << 5) + kk) * C_ + d]);

    __syncthreads();

    // ---- a[j] = SCALE * p0[i].p1[j], warp per j ----
    for (int j = warp; j <= i; j += 8) {
        const float* r = p1 + (size_t)j * C_;
        float v = s_p0[lane] * __ldg(&r[lane]) + s_p0[lane + 32] * __ldg(&r[lane + 32]);
#pragma unroll
        for (int o = 16; o; o >>= 1) v += __shfl_down_sync(0xffffffffu, v, o);
        if (lane == 0) s_a[j] = v * SCALE_;
    }
    __syncthreads();

    // ---- exact max via prefix max/min of s2 ----
    if (tid == 0) {
        float pmax = -3.4e38f, pmin = 3.4e38f, m = -3.4e38f;
        for (int j = 0; j <= i; j++) {
            float s = s_s2[j];
            pmax = fmaxf(pmax, s);
            pmin = fminf(pmin, s);
            float aj = s_a[j];
            m = fmaxf(m, (aj >= 0.f) ? aj * pmax : aj * pmin);
        }
        s_m = m;
    }
    __syncthreads();
    const float negm = -s_m;

    float zpart = 0.f;
    float partial = 0.f;

    const int nb = (i >> 3) + 1;  // number of 8-j batches

    // fill batch 0
    {
        const int j0 = 0;
#pragma unroll
        for (int r = 0; r < 4; r++) {
            int idx = tid + (r << 8);
            int jj = idx >> 7, k = idx & 127;
            int j = j0 + jj;
            float w = 0.f;
            if (j <= i && k <= j) {
                w = fast_exp(fmaf(s_a[j], s_s2[k], negm));
                zpart += w;
            }
            s_w[0][jj][k] = w;
        }
    }

    for (int bb = 0; bb < nb; bb++) {
        __syncthreads();
        const int cb = bb & 1;
        const int j0 = bb << 3;

        // consume batch bb
        for (int jj = 0; jj < JB_; jj++) {
            const int j = j0 + jj;
            if (j > i) break;
            if ((q << 5) <= j) {
                const float4* wr = (const float4*)&s_w[cb][jj][q << 5];
                float a0 = 0.f, a1 = 0.f, a2 = 0.f, a3 = 0.f;
#pragma unroll
                for (int r = 0; r < 8; r++) {
                    float4 w4 = wr[r];
                    a0 = fmaf(w4.x, v1r[4 * r + 0], a0);
                    a1 = fmaf(w4.y, v1r[4 * r + 1], a1);
                    a2 = fmaf(w4.z, v1r[4 * r + 2], a2);
                    a3 = fmaf(w4.w, v1r[4 * r + 3], a3);
                }
                partial = fmaf(s_v0[(j << 6) + d], (a0 + a1) + (a2 + a3), partial);
            }
        }

        // fill batch bb+1 into other buffer
        if (bb + 1 < nb) {
            const int j0n = (bb + 1) << 3;
#pragma unroll
            for (int r = 0; r < 4; r++) {
                int idx = tid + (r << 8);
                int jj = idx >> 7, k = idx & 127;
                int j = j0n + jj;
                float w = 0.f;
                if (j <= i && k <= j) {
                    w = fast_exp(fmaf(s_a[j], s_s2[k], negm));
                    zpart += w;
                }
                s_w[cb ^ 1][jj][k] = w;
            }
        }
    }

    // ---- reductions: Z scalar, partial over q ----
    __syncthreads();
    s_z[tid] = zpart;
    s_part[tid] = partial;
    __syncthreads();
    if (tid < 128) s_z[tid] += s_z[tid + 128];
    __syncthreads();
    if (tid < 64) s_z[tid] += s_z[tid + 64];
    __syncthreads();
    if (tid < 32) {
        float v = s_z[tid] + s_z[tid + 32];
#pragma unroll
        for (int o = 16; o; o >>= 1) v += __shfl_down_sync(0xffffffffu, v, o);
        if (tid == 0) s_z[0] = v;
    }
    __syncthreads();
    const float Z = s_z[0];

    if (tid < 64) {
        float y = ((s_part[tid] + s_part[tid + 64]) +
                   (s_part[tid + 128] + s_part[tid + 192])) / Z;
        g_y[(size_t)(b * T_ + i) * C_ + (size_t)h * HS_ + tid] = y;
    }
}

// ---------------------------------------------------------------------------
extern "C" void kernel_launch(void* const* d_in, const int* in_sizes, int n_in,
                              void* d_out, int out_size)
{
    (void)in_sizes; (void)n_in; (void)out_size;
    const float* x   = (const float*)d_in[0];
    const float* Wp0 = (const float*)d_in[1];
    const float* Wp1 = (const float*)d_in[2];
    const float* Wp2 = (const float*)d_in[3];
    const float* Wv0 = (const float*)d_in[4];
    const float* Wv1 = (const float*)d_in[5];
    const float* Wc  = (const float*)d_in[6];
    float* out = (float*)d_out;

    proj_kernel<<<dim3(C_ / BNg, (B_ * T_) / BMg, 3), 256>>>(x, Wp0, Wp1, Wp2);
    vproj_kernel<<<dim3(1, (B_ * T_ * NH_) / BMg, 2), 256>>>(Wv0, Wv1);
    s2_kernel<<<(B_ * T_ * NH_ * 32 + 255) / 256, 256>>>();
    attn_kernel<<<dim3(T_, NH_, B_), 256>>>();
    out_kernel<<<dim3(C_ / BNg, (B_ * T_) / BMg), 256>>>(Wc, out);
}

// round 3
// speedup vs baseline: 1.4800x; 1.0003x over previous
#include <cuda_runtime.h>

#define B_  4
#define T_  128
#define C_  512
#define NH_ 8
#define HS_ 64
#define BTC (B_*T_*C_)
#define SCALE_ 0.125f
#define JB_ 8   // j rows per batch in attn kernel

// Scratch (allocation-free rule: __device__ globals)
__device__ float g_P[3 * BTC];      // p0,p1,p2 in (B,T,C) layout
__device__ float g_V[2 * BTC];      // V0,V1 in (B,T,C) layout
__device__ float g_s2[B_ * NH_ * T_];
__device__ float g_y[BTC];          // (B,T,C) layout

// ---------------------------------------------------------------------------
// Packed fp32x2 helpers (Blackwell FFMA2 path — PTX only)
// ---------------------------------------------------------------------------
__device__ __forceinline__ unsigned long long pack2(float lo, float hi)
{
    unsigned long long r;
    asm("mov.b64 %0, {%1, %2};" : "=l"(r) : "f"(lo), "f"(hi));
    return r;
}
__device__ __forceinline__ unsigned long long fma2_(unsigned long long a,
                                                    unsigned long long b,
                                                    unsigned long long c)
{
    unsigned long long d;
    asm("fma.rn.f32x2 %0, %1, %2, %3;" : "=l"(d) : "l"(a), "l"(b), "l"(c));
    return d;
}
__device__ __forceinline__ unsigned long long add2_(unsigned long long a,
                                                    unsigned long long b)
{
    unsigned long long d;
    asm("add.rn.f32x2 %0, %1, %2;" : "=l"(d) : "l"(a), "l"(b));
    return d;
}
__device__ __forceinline__ float2 unpack2(unsigned long long v)
{
    float lo, hi;
    asm("mov.b64 {%0, %1}, %2;" : "=f"(lo), "=f"(hi) : "l"(v));
    return make_float2(lo, hi);
}

// ---------------------------------------------------------------------------
// Generic fp32 GEMM body: C[M,N] = A[M,K] @ B[K,N], row-major.
// Tile 64x64, BK=16, 256 threads, 4x4 per thread, f32x2 inner FMAs.
// ---------------------------------------------------------------------------
#define BMg 64
#define BNg 64
#define BKg 16

__device__ __forceinline__ void gemm_body(
    const float* __restrict__ A, const float* __restrict__ Bm,
    float* __restrict__ Cm, int M, int N, int K)
{
    __shared__ float As[BKg][BMg];
    __shared__ float Bs[BKg][BNg];

    const int tid = threadIdx.x;
    const int tx = tid & 15;
    const int ty = tid >> 4;
    const int row0 = blockIdx.y * BMg;
    const int col0 = blockIdx.x * BNg;

    const int lr = tid >> 2;
    const int lk = (tid & 3) * 4;
    const int kr = tid >> 4;
    const int nc = (tid & 15) * 4;

    unsigned long long acc2[4][2];
#pragma unroll
    for (int r = 0; r < 4; r++) { acc2[r][0] = 0ull; acc2[r][1] = 0ull; }

    for (int k0 = 0; k0 < K; k0 += BKg) {
        float4 av = *(const float4*)&A[(size_t)(row0 + lr) * K + k0 + lk];
        As[lk + 0][lr] = av.x;
        As[lk + 1][lr] = av.y;
        As[lk + 2][lr] = av.z;
        As[lk + 3][lr] = av.w;
        float4 bv = *(const float4*)&Bm[(size_t)(k0 + kr) * N + col0 + nc];
        *(float4*)&Bs[kr][nc] = bv;
        __syncthreads();

#pragma unroll
        for (int kk = 0; kk < BKg; kk++) {
            float4 a4 = *(const float4*)&As[kk][ty * 4];
            ulonglong2 b2 = *(const ulonglong2*)&Bs[kk][tx * 4];
            float ar[4] = {a4.x, a4.y, a4.z, a4.w};
#pragma unroll
            for (int r = 0; r < 4; r++) {
                unsigned long long ap = pack2(ar[r], ar[r]);
                acc2[r][0] = fma2_(ap, b2.x, acc2[r][0]);
                acc2[r][1] = fma2_(ap, b2.y, acc2[r][1]);
            }
        }
        __syncthreads();
    }

#pragma unroll
    for (int r = 0; r < 4; r++) {
        float2 e0 = unpack2(acc2[r][0]);
        float2 e1 = unpack2(acc2[r][1]);
        float4 out = make_float4(e0.x, e0.y, e1.x, e1.y);
        *(float4*)&Cm[(size_t)(row0 + ty * 4 + r) * N + col0 + tx * 4] = out;
    }
}

__global__ void proj_kernel(const float* __restrict__ x,
                            const float* __restrict__ W0,
                            const float* __restrict__ W1,
                            const float* __restrict__ W2)
{
    const int z = blockIdx.z;
    const float* W = (z == 0) ? W0 : ((z == 1) ? W1 : W2);
    gemm_body(x, W, g_P + (size_t)z * BTC, B_ * T_, C_, C_);
}

__global__ void vproj_kernel(const float* __restrict__ Wv0,
                             const float* __restrict__ Wv1)
{
    const int z = blockIdx.z;
    gemm_body(g_P + (size_t)(z + 1) * BTC, z ? Wv1 : Wv0,
              g_V + (size_t)z * BTC, B_ * T_ * NH_, HS_, HS_);
}

__global__ void out_kernel(const float* __restrict__ Wc, float* __restrict__ out)
{
    gemm_body(g_y, Wc, out, B_ * T_, C_, C_);
}

// ---------------------------------------------------------------------------
// s2[b,h,t] = sum_d p2[b,h,t,d]
// ---------------------------------------------------------------------------
__global__ void s2_kernel()
{
    const int warp = (blockIdx.x * blockDim.x + threadIdx.x) >> 5;
    const int lane = threadIdx.x & 31;
    if (warp >= B_ * T_ * NH_) return;
    const float* row = g_P + (size_t)2 * BTC + (size_t)warp * HS_;
    float v = row[lane] + row[lane + 32];
#pragma unroll
    for (int o = 16; o; o >>= 1) v += __shfl_down_sync(0xffffffffu, v, o);
    if (lane == 0) {
        const int b = warp / (T_ * NH_);
        const int t = (warp / NH_) % T_;
        const int h = warp % NH_;
        g_s2[(b * NH_ + h) * T_ + t] = v;
    }
}

// ---------------------------------------------------------------------------
// Higher-order attention:
//   block = (b,h,i), 256 threads = (d in [0,64), q in [0,4)).
//   Thread (d,q) owns interleaved k-chunks {16m+4q .. 16m+4q+3}, m=0..7,
//   holding V1[k][d] as 16 packed f32x2 registers.
//   y_d = (1/Z) * sum_{j<=i} V0[j,d] * sum_{k<=j} w[j,k] * V1[k,d]
//   w rows produced in 8-j batches into double-buffered smem (zero padded),
//   consumed via LDS.128 (broadcast) + packed FFMA2. One sync per batch.
// ---------------------------------------------------------------------------
__global__ __launch_bounds__(256) void attn_kernel()
{
    const int i = T_ - 1 - blockIdx.x;   // big-i first (load balance)
    const int h = blockIdx.y;
    const int b = blockIdx.z;
    const int tid = threadIdx.x;
    const int d = tid & 63;
    const int q = tid >> 6;
    const int lane = tid & 31;
    const int warp = tid >> 5;

    __shared__ float s_w[2][JB_][128];   // w batches (zero-padded)
    __shared__ float s_v0[T_ * 64];      // V0[j][d]
    __shared__ float s_s2[T_];
    __shared__ float s_a[T_];
    __shared__ float s_p0[HS_];
    __shared__ float s_red[256];         // pmax scan / z reduce
    __shared__ float s_red2[256];        // pmin scan / partial reduce
    __shared__ float s_wred[8];
    __shared__ float s_m, s_zz;

    const size_t headoff = (size_t)(b * T_) * C_ + (size_t)h * HS_;
    const float* p0 = g_P + headoff + (size_t)i * C_;
    const float* p1 = g_P + BTC + headoff;
    const float* v0 = g_V + headoff;
    const float* v1 = g_V + BTC + headoff;
    const float* s2r = g_s2 + (b * NH_ + h) * T_;

    // ---- loads ----
    if (tid < 64) s_p0[tid] = p0[tid];
    if (tid < 128) s_s2[tid] = s2r[tid];
    for (int idx = tid; idx < (i + 1) * 64; idx += 256)
        s_v0[idx] = __ldg(&v0[(size_t)(idx >> 6) * C_ + (idx & 63)]);

    // V1 interleaved chunks into packed registers (coalesced per warp)
    unsigned long long v1p[16];
#pragma unroll
    for (int m = 0; m < 8; m++) {
        const int k0 = (m << 4) + (q << 2);
        float x0 = __ldg(&v1[(size_t)(k0 + 0) * C_ + d]);
        float x1 = __ldg(&v1[(size_t)(k0 + 1) * C_ + d]);
        float x2 = __ldg(&v1[(size_t)(k0 + 2) * C_ + d]);
        float x3 = __ldg(&v1[(size_t)(k0 + 3) * C_ + d]);
        v1p[2 * m]     = pack2(x0, x1);
        v1p[2 * m + 1] = pack2(x2, x3);
    }
    __syncthreads();

    // ---- a[j] = SCALE * p0[i].p1[j], warp per j ----
    for (int j = warp; j <= i; j += 8) {
        const float* r = p1 + (size_t)j * C_;
        float v = fmaf(s_p0[lane], __ldg(&r[lane]),
                       s_p0[lane + 32] * __ldg(&r[lane + 32]));
#pragma unroll
        for (int o = 16; o; o >>= 1) v += __shfl_down_sync(0xffffffffu, v, o);
        if (lane == 0) s_a[j] = v * SCALE_;
    }
    __syncthreads();

    // ---- prefix max/min of s2 (warp 0, shuffle scan) ----
    if (warp == 0) {
        float4 s4 = *(const float4*)&s_s2[lane << 2];
        float px1 = fmaxf(s4.x, s4.y), px2 = fmaxf(px1, s4.z), px3 = fmaxf(px2, s4.w);
        float pn1 = fminf(s4.x, s4.y), pn2 = fminf(pn1, s4.z), pn3 = fminf(pn2, s4.w);
        float im = px3, in_ = pn3;
#pragma unroll
        for (int off = 1; off < 32; off <<= 1) {
            float tm = __shfl_up_sync(0xffffffffu, im, off);
            float tn = __shfl_up_sync(0xffffffffu, in_, off);
            if (lane >= off) { im = fmaxf(im, tm); in_ = fminf(in_, tn); }
        }
        float em = __shfl_up_sync(0xffffffffu, im, 1);
        float en = __shfl_up_sync(0xffffffffu, in_, 1);
        if (lane == 0) { em = -3.4e38f; en = 3.4e38f; }
        s_red [(lane << 2) + 0] = fmaxf(em, s4.x);
        s_red [(lane << 2) + 1] = fmaxf(em, px1);
        s_red [(lane << 2) + 2] = fmaxf(em, px2);
        s_red [(lane << 2) + 3] = fmaxf(em, px3);
        s_red2[(lane << 2) + 0] = fminf(en, s4.x);
        s_red2[(lane << 2) + 1] = fminf(en, pn1);
        s_red2[(lane << 2) + 2] = fminf(en, pn2);
        s_red2[(lane << 2) + 3] = fminf(en, pn3);
    }
    __syncthreads();

    // exact max over valid triples: max_j ( a[j]>=0 ? a[j]*pmax[j] : a[j]*pmin[j] )
    float cand = -3.4e38f;
    if (tid <= i) {
        float aj = s_a[tid];
        cand = (aj >= 0.f) ? aj * s_red[tid] : aj * s_red2[tid];
    }
#pragma unroll
    for (int o = 16; o; o >>= 1)
        cand = fmaxf(cand, __shfl_down_sync(0xffffffffu, cand, o));
    if (lane == 0) s_wred[warp] = cand;
    __syncthreads();
    if (tid == 0) {
        float m = s_wred[0];
#pragma unroll
        for (int w = 1; w < 8; w++) m = fmaxf(m, s_wred[w]);
        s_m = m;
    }
    __syncthreads();
    const float negm = -s_m;

    float zpart = 0.f;
    unsigned long long part2 = 0ull;

    const int nb = (i >> 3) + 1;

    // fill batch 0
#pragma unroll
    for (int r = 0; r < 4; r++) {
        int idx = (r << 8) + tid;
        int jj = idx >> 7, k = idx & 127;
        float w = 0.f;
        if (jj <= i && k <= jj) {
            w = __expf(fmaf(s_a[jj], s_s2[k], negm));
            zpart += w;
        }
        s_w[0][jj][k] = w;
    }

    for (int bb = 0; bb < nb; bb++) {
        __syncthreads();
        const int cb = bb & 1;
        const int j0 = bb << 3;

        // consume batch bb
        for (int jj = 0; jj < JB_; jj++) {
            const int j = j0 + jj;
            if (j > i) break;
            int Mq = (j - (q << 2) + 16) >> 4;
            if (Mq > 8) Mq = 8;
            unsigned long long acc0 = 0ull, acc1 = 0ull;
            const float* wrow = &s_w[cb][jj][q << 2];
            for (int m = 0; m < Mq; m++) {
                ulonglong2 w2 = *(const ulonglong2*)(wrow + (m << 4));
                acc0 = fma2_(w2.x, v1p[2 * m],     acc0);
                acc1 = fma2_(w2.y, v1p[2 * m + 1], acc1);
            }
            float vj = s_v0[(j << 6) + d];
            part2 = fma2_(pack2(vj, vj), add2_(acc0, acc1), part2);
        }

        // fill batch bb+1
        if (bb + 1 < nb) {
            const int j0n = (bb + 1) << 3;
#pragma unroll
            for (int r = 0; r < 4; r++) {
                int idx = (r << 8) + tid;
                int jj = idx >> 7, k = idx & 127;
                int j = j0n + jj;
                float w = 0.f;
                if (j <= i && k <= j) {
                    w = __expf(fmaf(s_a[j], s_s2[k], negm));
                    zpart += w;
                }
                s_w[cb ^ 1][jj][k] = w;
            }
        }
    }

    // ---- reductions: Z scalar, partial over q ----
    __syncthreads();
    float2 pp = unpack2(part2);
    s_red[tid] = zpart;
    s_red2[tid] = pp.x + pp.y;
    __syncthreads();
    if (tid < 128) s_red[tid] += s_red[tid + 128];
    __syncthreads();
    if (tid < 64) s_red[tid] += s_red[tid + 64];
    __syncthreads();
    if (tid < 32) {
        float v = s_red[tid] + s_red[tid + 32];
#pragma unroll
        for (int o = 16; o; o >>= 1) v += __shfl_down_sync(0xffffffffu, v, o);
        if (tid == 0) s_zz = v;
    }
    __syncthreads();
    const float Z = s_zz;

    if (tid < 64) {
        float y = ((s_red2[tid] + s_red2[tid + 64]) +
                   (s_red2[tid + 128] + s_red2[tid + 192])) / Z;
        g_y[(size_t)(b * T_ + i) * C_ + (size_t)h * HS_ + tid] = y;
    }
}

// ---------------------------------------------------------------------------
extern "C" void kernel_launch(void* const* d_in, const int* in_sizes, int n_in,
                              void* d_out, int out_size)
{
    (void)in_sizes; (void)n_in; (void)out_size;
    const float* x   = (const float*)d_in[0];
    const float* Wp0 = (const float*)d_in[1];
    const float* Wp1 = (const float*)d_in[2];
    const float* Wp2 = (const float*)d_in[3];
    const float* Wv0 = (const float*)d_in[4];
    const float* Wv1 = (const float*)d_in[5];
    const float* Wc  = (const float*)d_in[6];
    float* out = (float*)d_out;

    proj_kernel<<<dim3(C_ / BNg, (B_ * T_) / BMg, 3), 256>>>(x, Wp0, Wp1, Wp2);
    vproj_kernel<<<dim3(1, (B_ * T_ * NH_) / BMg, 2), 256>>>(Wv0, Wv1);
    s2_kernel<<<(B_ * T_ * NH_ * 32 + 255) / 256, 256>>>();
    attn_kernel<<<dim3(T_, NH_, B_), 256>>>();
    out_kernel<<<dim3(C_ / BNg, (B_ * T_) / BMg), 256>>>(Wc, out);
}

// round 4
// speedup vs baseline: 1.6433x; 1.1103x over previous
#include <cuda_runtime.h>

#define B_  4
#define T_  128
#define C_  512
#define NH_ 8
#define HS_ 64
#define BTC (B_*T_*C_)
#define SCALE_ 0.125f
#define LOG2E_ 1.4426950408889634f
#define JB_ 8   // j rows per batch in attn kernel

// Scratch (allocation-free rule: __device__ globals)
__device__ float g_P[3 * BTC];      // p0,p1,p2 in (B,T,C) layout
__device__ float g_V[2 * BTC];      // V0,V1 in (B,T,C) layout
__device__ float g_s2[B_ * NH_ * T_];
__device__ float g_y[BTC];          // (B,T,C) layout

// ---------------------------------------------------------------------------
// Packed fp32x2 helpers (Blackwell FFMA2 path — PTX only)
// ---------------------------------------------------------------------------
__device__ __forceinline__ unsigned long long pack2(float lo, float hi)
{
    unsigned long long r;
    asm("mov.b64 %0, {%1, %2};" : "=l"(r) : "f"(lo), "f"(hi));
    return r;
}
__device__ __forceinline__ unsigned long long fma2_(unsigned long long a,
                                                    unsigned long long b,
                                                    unsigned long long c)
{
    unsigned long long d;
    asm("fma.rn.f32x2 %0, %1, %2, %3;" : "=l"(d) : "l"(a), "l"(b), "l"(c));
    return d;
}
__device__ __forceinline__ unsigned long long add2_(unsigned long long a,
                                                    unsigned long long b)
{
    unsigned long long d;
    asm("add.rn.f32x2 %0, %1, %2;" : "=l"(d) : "l"(a), "l"(b));
    return d;
}
__device__ __forceinline__ float2 unpack2(unsigned long long v)
{
    float lo, hi;
    asm("mov.b64 {%0, %1}, %2;" : "=f"(lo), "=f"(hi) : "l"(v));
    return make_float2(lo, hi);
}
__device__ __forceinline__ float ex2_(float x)
{
    float r;
    asm("ex2.approx.f32 %0, %1;" : "=f"(r) : "f"(x));
    return r;
}

// ---------------------------------------------------------------------------
// Templated fp32 GEMM body: C[M,N] = A[M,K] @ B[K,N], row-major.
// Tile (16*TM) x 64, BK=16, 256 threads, TM x 4 per thread, f32x2 FMAs.
// ---------------------------------------------------------------------------
#define BNg 64
#define BKg 16

template<int TM>
__device__ __forceinline__ void gemm_body_t(
    const float* __restrict__ A, const float* __restrict__ Bm,
    float* __restrict__ Cm, int M, int N, int K)
{
    constexpr int BM = 16 * TM;
    __shared__ float As[BKg][BM];
    __shared__ float Bs[BKg][BNg];

    const int tid = threadIdx.x;
    const int tx = tid & 15;
    const int ty = tid >> 4;
    const int row0 = blockIdx.y * BM;
    const int col0 = blockIdx.x * BNg;

    const int kr = tid >> 4;
    const int nc = (tid & 15) * 4;

    unsigned long long acc2[TM][2];
#pragma unroll
    for (int r = 0; r < TM; r++) { acc2[r][0] = 0ull; acc2[r][1] = 0ull; }

    for (int k0 = 0; k0 < K; k0 += BKg) {
        // A tile: BM rows x 16 k  (BM*4 float4 loads)
#pragma unroll
        for (int l = tid; l < BM * 4; l += 256) {
            const int lr = l >> 2;
            const int lk = (l & 3) << 2;
            float4 av = *(const float4*)&A[(size_t)(row0 + lr) * K + k0 + lk];
            As[lk + 0][lr] = av.x;
            As[lk + 1][lr] = av.y;
            As[lk + 2][lr] = av.z;
            As[lk + 3][lr] = av.w;
        }
        float4 bv = *(const float4*)&Bm[(size_t)(k0 + kr) * N + col0 + nc];
        *(float4*)&Bs[kr][nc] = bv;
        __syncthreads();

#pragma unroll
        for (int kk = 0; kk < BKg; kk++) {
            ulonglong2 b2 = *(const ulonglong2*)&Bs[kk][tx * 4];
#pragma unroll
            for (int r = 0; r < TM; r++) {
                float a = As[kk][ty * TM + r];
                unsigned long long ap = pack2(a, a);
                acc2[r][0] = fma2_(ap, b2.x, acc2[r][0]);
                acc2[r][1] = fma2_(ap, b2.y, acc2[r][1]);
            }
        }
        __syncthreads();
    }

#pragma unroll
    for (int r = 0; r < TM; r++) {
        float2 e0 = unpack2(acc2[r][0]);
        float2 e1 = unpack2(acc2[r][1]);
        float4 out = make_float4(e0.x, e0.y, e1.x, e1.y);
        *(float4*)&Cm[(size_t)(row0 + ty * TM + r) * N + col0 + tx * 4] = out;
    }
}

__global__ void proj_kernel(const float* __restrict__ x,
                            const float* __restrict__ W0,
                            const float* __restrict__ W1,
                            const float* __restrict__ W2)
{
    const int z = blockIdx.z;
    const float* W = (z == 0) ? W0 : ((z == 1) ? W1 : W2);
    gemm_body_t<4>(x, W, g_P + (size_t)z * BTC, B_ * T_, C_, C_);
}

__global__ void vproj_kernel(const float* __restrict__ Wv0,
                             const float* __restrict__ Wv1)
{
    const int z = blockIdx.z;
    gemm_body_t<2>(g_P + (size_t)(z + 1) * BTC, z ? Wv1 : Wv0,
                   g_V + (size_t)z * BTC, B_ * T_ * NH_, HS_, HS_);
}

__global__ void out_kernel(const float* __restrict__ Wc, float* __restrict__ out)
{
    gemm_body_t<2>(g_y, Wc, out, B_ * T_, C_, C_);
}

// ---------------------------------------------------------------------------
// s2[b,h,t] = sum_d p2[b,h,t,d]
// ---------------------------------------------------------------------------
__global__ void s2_kernel()
{
    const int warp = (blockIdx.x * blockDim.x + threadIdx.x) >> 5;
    const int lane = threadIdx.x & 31;
    if (warp >= B_ * T_ * NH_) return;
    const float* row = g_P + (size_t)2 * BTC + (size_t)warp * HS_;
    float v = row[lane] + row[lane + 32];
#pragma unroll
    for (int o = 16; o; o >>= 1) v += __shfl_down_sync(0xffffffffu, v, o);
    if (lane == 0) {
        const int b = warp / (T_ * NH_);
        const int t = (warp / NH_) % T_;
        const int h = warp % NH_;
        g_s2[(b * NH_ + h) * T_ + t] = v;
    }
}

// ---------------------------------------------------------------------------
// Higher-order attention:
//   block = (b,h,i), 256 threads = (d in [0,64), q in [0,4)).
//   Thread (d,q) owns contiguous k in [32q, 32q+32), V1[k][d] in 16 f32x2 regs.
//   s_a pre-scaled by SCALE*log2e; w = ex2(fma(a2[j], s2[k], negm2)).
//   w rows produced in 8-j batches into double-buffered zero-padded smem,
//   consumed fully unrolled (16 FFMA2 + 8 LDS.128 per active row).
// ---------------------------------------------------------------------------
__global__ __launch_bounds__(256) void attn_kernel()
{
    const int i = T_ - 1 - blockIdx.x;   // big-i first (load balance)
    const int h = blockIdx.y;
    const int b = blockIdx.z;
    const int tid = threadIdx.x;
    const int d = tid & 63;
    const int q = tid >> 6;
    const int lane = tid & 31;
    const int warp = tid >> 5;

    __shared__ float s_w[2][JB_][128];   // w batches (zero-padded)
    __shared__ float s_v0[T_ * 64];      // V0[j][d], zero-padded to batch end
    __shared__ float s_s2[T_];
    __shared__ float s_a[T_];            // pre-scaled: a * SCALE * log2e
    __shared__ float s_p0[HS_];
    __shared__ float s_red[256];
    __shared__ float s_red2[256];
    __shared__ float s_wred[8];
    __shared__ float s_m, s_zz;

    const size_t headoff = (size_t)(b * T_) * C_ + (size_t)h * HS_;
    const float* p0 = g_P + headoff + (size_t)i * C_;
    const float* p1 = g_P + BTC + headoff;
    const float* v0 = g_V + headoff;
    const float* v1 = g_V + BTC + headoff;
    const float* s2r = g_s2 + (b * NH_ + h) * T_;

    const int nb = (i >> 3) + 1;         // number of 8-j batches
    const int nrows = nb << 3;           // rows incl. zero padding

    // ---- loads ----
    if (tid < 64) s_p0[tid] = p0[tid];
    if (tid < 128) s_s2[tid] = s2r[tid];
    // V0 rows [0..i] + zero pad to nrows, float4 granularity
    for (int idx = tid; idx < (nrows << 4); idx += 256) {
        const int row = idx >> 4;
        const int c4 = (idx & 15) << 2;
        float4 v = make_float4(0.f, 0.f, 0.f, 0.f);
        if (row <= i) v = __ldg((const float4*)&v0[(size_t)row * C_ + c4]);
        *(float4*)&s_v0[(row << 6) + c4] = v;
    }

    // V1 contiguous chunk into packed registers (coalesced per warp)
    unsigned long long v1p[16];
#pragma unroll
    for (int m = 0; m < 16; m++) {
        const int k0 = (q << 5) + (m << 1);
        float x0 = __ldg(&v1[(size_t)(k0 + 0) * C_ + d]);
        float x1 = __ldg(&v1[(size_t)(k0 + 1) * C_ + d]);
        v1p[m] = pack2(x0, x1);
    }
    __syncthreads();

    // ---- a[j] = SCALE*log2e * p0[i].p1[j], warp per j ----
    for (int j = warp; j <= i; j += 8) {
        const float* r = p1 + (size_t)j * C_;
        float v = fmaf(s_p0[lane], __ldg(&r[lane]),
                       s_p0[lane + 32] * __ldg(&r[lane + 32]));
#pragma unroll
        for (int o = 16; o; o >>= 1) v += __shfl_down_sync(0xffffffffu, v, o);
        if (lane == 0) s_a[j] = v * (SCALE_ * LOG2E_);
    }
    __syncthreads();

    // ---- prefix max/min of s2 (warp 0, shuffle scan) ----
    if (warp == 0) {
        float4 s4 = *(const float4*)&s_s2[lane << 2];
        float px1 = fmaxf(s4.x, s4.y), px2 = fmaxf(px1, s4.z), px3 = fmaxf(px2, s4.w);
        float pn1 = fminf(s4.x, s4.y), pn2 = fminf(pn1, s4.z), pn3 = fminf(pn2, s4.w);
        float im = px3, in_ = pn3;
#pragma unroll
        for (int off = 1; off < 32; off <<= 1) {
            float tm = __shfl_up_sync(0xffffffffu, im, off);
            float tn = __shfl_up_sync(0xffffffffu, in_, off);
            if (lane >= off) { im = fmaxf(im, tm); in_ = fminf(in_, tn); }
        }
        float em = __shfl_up_sync(0xffffffffu, im, 1);
        float en = __shfl_up_sync(0xffffffffu, in_, 1);
        if (lane == 0) { em = -3.4e38f; en = 3.4e38f; }
        s_red [(lane << 2) + 0] = fmaxf(em, s4.x);
        s_red [(lane << 2) + 1] = fmaxf(em, px1);
        s_red [(lane << 2) + 2] = fmaxf(em, px2);
        s_red [(lane << 2) + 3] = fmaxf(em, px3);
        s_red2[(lane << 2) + 0] = fminf(en, s4.x);
        s_red2[(lane << 2) + 1] = fminf(en, pn1);
        s_red2[(lane << 2) + 2] = fminf(en, pn2);
        s_red2[(lane << 2) + 3] = fminf(en, pn3);
    }
    __syncthreads();

    // exact max (in log2 units) over valid triples
    float cand = -3.4e38f;
    if (tid <= i) {
        float aj = s_a[tid];
        cand = (aj >= 0.f) ? aj * s_red[tid] : aj * s_red2[tid];
    }
#pragma unroll
    for (int o = 16; o; o >>= 1)
        cand = fmaxf(cand, __shfl_down_sync(0xffffffffu, cand, o));
    if (lane == 0) s_wred[warp] = cand;
    __syncthreads();
    if (tid == 0) {
        float m = s_wred[0];
#pragma unroll
        for (int w = 1; w < 8; w++) m = fmaxf(m, s_wred[w]);
        s_m = m;
    }
    __syncthreads();
    const float negm2 = -s_m;

    float zpart = 0.f;
    unsigned long long part2 = 0ull;

    // fill thread geometry: fixed k, two base jj rows
    const int kf = tid & 127;
    const int jjf = tid >> 7;            // 0 or 1
    const float s2k = s_s2[kf];

    // fill batch 0
    {
        float* wb = &s_w[0][0][0];
#pragma unroll
        for (int r = 0; r < 4; r++) {
            const int jj = jjf + (r << 1);
            float e = ex2_(fmaf(s_a[jj], s2k, negm2));
            float w = (kf <= jj && jj <= i) ? e : 0.f;
            zpart += w;
            wb[(jj << 7) + kf] = w;
        }
    }

    for (int bb = 0; bb < nb; bb++) {
        __syncthreads();
        const int cb = bb & 1;
        const int j0 = bb << 3;
        const float* wbase = &s_w[cb][0][q << 5];

        // consume batch bb: all 8 rows, fully unrolled, zero rows are free
#pragma unroll
        for (int jj = 0; jj < JB_; jj++) {
            const int j = j0 + jj;
            if ((q << 5) <= j) {          // warp-uniform skip
                const ulonglong2* wr = (const ulonglong2*)(wbase + (jj << 7));
                ulonglong2 w0 = wr[0], w1 = wr[1], w2v = wr[2], w3 = wr[3];
                unsigned long long a0, a1, a2v, a3;
                a0 = fma2_(w0.x, v1p[0], 0ull);
                a1 = fma2_(w0.y, v1p[1], 0ull);
                a2v = fma2_(w1.x, v1p[2], 0ull);
                a3 = fma2_(w1.y, v1p[3], 0ull);
                a0 = fma2_(w2v.x, v1p[4], a0);
                a1 = fma2_(w2v.y, v1p[5], a1);
                a2v = fma2_(w3.x, v1p[6], a2v);
                a3 = fma2_(w3.y, v1p[7], a3);
                ulonglong2 w4 = wr[4], w5 = wr[5], w6 = wr[6], w7 = wr[7];
                a0 = fma2_(w4.x, v1p[8], a0);
                a1 = fma2_(w4.y, v1p[9], a1);
                a2v = fma2_(w5.x, v1p[10], a2v);
                a3 = fma2_(w5.y, v1p[11], a3);
                a0 = fma2_(w6.x, v1p[12], a0);
                a1 = fma2_(w6.y, v1p[13], a1);
                a2v = fma2_(w7.x, v1p[14], a2v);
                a3 = fma2_(w7.y, v1p[15], a3);
                float vj = s_v0[(j << 6) + d];
                part2 = fma2_(pack2(vj, vj),
                              add2_(add2_(a0, a1), add2_(a2v, a3)), part2);
            }
        }

        // fill batch bb+1
        if (bb + 1 < nb) {
            const int j0n = (bb + 1) << 3;
            float* wb = &s_w[cb ^ 1][0][0];
#pragma unroll
            for (int r = 0; r < 4; r++) {
                const int jj = jjf + (r << 1);
                const int j = j0n + jj;
                float e = ex2_(fmaf(s_a[j], s2k, negm2));
                float w = (kf <= j && j <= i) ? e : 0.f;
                zpart += w;
                wb[(jj << 7) + kf] = w;
            }
        }
    }

    // ---- reductions: Z scalar, partial over q ----
    __syncthreads();
    float2 pp = unpack2(part2);
    s_red[tid] = zpart;
    s_red2[tid] = pp.x + pp.y;
    __syncthreads();
    if (tid < 128) s_red[tid] += s_red[tid + 128];
    __syncthreads();
    if (tid < 64) s_red[tid] += s_red[tid + 64];
    __syncthreads();
    if (tid < 32) {
        float v = s_red[tid] + s_red[tid + 32];
#pragma unroll
        for (int o = 16; o; o >>= 1) v += __shfl_down_sync(0xffffffffu, v, o);
        if (tid == 0) s_zz = v;
    }
    __syncthreads();
    const float Z = s_zz;

    if (tid < 64) {
        float y = ((s_red2[tid] + s_red2[tid + 64]) +
                   (s_red2[tid + 128] + s_red2[tid + 192])) / Z;
        g_y[(size_t)(b * T_ + i) * C_ + (size_t)h * HS_ + tid] = y;
    }
}

// ---------------------------------------------------------------------------
extern "C" void kernel_launch(void* const* d_in, const int* in_sizes, int n_in,
                              void* d_out, int out_size)
{
    (void)in_sizes; (void)n_in; (void)out_size;
    const float* x   = (const float*)d_in[0];
    const float* Wp0 = (const float*)d_in[1];
    const float* Wp1 = (const float*)d_in[2];
    const float* Wp2 = (const float*)d_in[3];
    const float* Wv0 = (const float*)d_in[4];
    const float* Wv1 = (const float*)d_in[5];
    const float* Wc  = (const float*)d_in[6];
    float* out = (float*)d_out;

    proj_kernel<<<dim3(C_ / BNg, (B_ * T_) / 64, 3), 256>>>(x, Wp0, Wp1, Wp2);
    vproj_kernel<<<dim3(1, (B_ * T_ * NH_) / 32, 2), 256>>>(Wv0, Wv1);
    s2_kernel<<<(B_ * NH_ * T_ * 32 + 255) / 256, 256>>>();
    attn_kernel<<<dim3(T_, NH_, B_), 256>>>();
    out_kernel<<<dim3(C_ / BNg, (B_ * T_) / 32), 256>>>(Wc, out);
}

// round 5
// speedup vs baseline: 2.5078x; 1.5260x over previous
#include <cuda_runtime.h>
#include <stdint.h>

#define B_  4
#define T_  128
#define C_  512
#define NH_ 8
#define HS_ 64
#define BTC (B_*T_*C_)
#define SCALE_ 0.125f
#define LOG2E_ 1.4426950408889634f

// Scratch (allocation-free rule: __device__ globals)
__device__ float g_P[3 * BTC];      // p0,p1,p2 in (B,T,C) layout
__device__ float g_V[2 * BTC];      // V0,V1 in (B,T,C) layout
__device__ float g_s2[B_ * NH_ * T_];
__device__ float g_y[BTC];          // (B,T,C) layout

// ---------------------------------------------------------------------------
// Packed fp32x2 helpers (GEMM kernels)
// ---------------------------------------------------------------------------
__device__ __forceinline__ unsigned long long pack2(float lo, float hi)
{
    unsigned long long r;
    asm("mov.b64 %0, {%1, %2};" : "=l"(r) : "f"(lo), "f"(hi));
    return r;
}
__device__ __forceinline__ unsigned long long fma2_(unsigned long long a,
                                                    unsigned long long b,
                                                    unsigned long long c)
{
    unsigned long long d;
    asm("fma.rn.f32x2 %0, %1, %2, %3;" : "=l"(d) : "l"(a), "l"(b), "l"(c));
    return d;
}
__device__ __forceinline__ float2 unpack2(unsigned long long v)
{
    float lo, hi;
    asm("mov.b64 {%0, %1}, %2;" : "=f"(lo), "=f"(hi) : "l"(v));
    return make_float2(lo, hi);
}
__device__ __forceinline__ float ex2_(float x)
{
    float r;
    asm("ex2.approx.f32 %0, %1;" : "=f"(r) : "f"(x));
    return r;
}
__device__ __forceinline__ uint32_t tf32_(float x)
{
    uint32_t r;
    asm("cvt.rna.tf32.f32 %0, %1;" : "=r"(r) : "f"(x));
    return r;
}

// ---------------------------------------------------------------------------
// Templated fp32 GEMM body: C[M,N] = A[M,K] @ B[K,N], row-major.
// ---------------------------------------------------------------------------
#define BNg 64
#define BKg 16

template<int TM>
__device__ __forceinline__ void gemm_body_t(
    const float* __restrict__ A, const float* __restrict__ Bm,
    float* __restrict__ Cm, int M, int N, int K)
{
    constexpr int BM = 16 * TM;
    __shared__ float As[BKg][BM];
    __shared__ float Bs[BKg][BNg];

    const int tid = threadIdx.x;
    const int tx = tid & 15;
    const int ty = tid >> 4;
    const int row0 = blockIdx.y * BM;
    const int col0 = blockIdx.x * BNg;

    const int kr = tid >> 4;
    const int nc = (tid & 15) * 4;

    unsigned long long acc2[TM][2];
#pragma unroll
    for (int r = 0; r < TM; r++) { acc2[r][0] = 0ull; acc2[r][1] = 0ull; }

    for (int k0 = 0; k0 < K; k0 += BKg) {
#pragma unroll
        for (int l = tid; l < BM * 4; l += 256) {
            const int lr = l >> 2;
            const int lk = (l & 3) << 2;
            float4 av = *(const float4*)&A[(size_t)(row0 + lr) * K + k0 + lk];
            As[lk + 0][lr] = av.x;
            As[lk + 1][lr] = av.y;
            As[lk + 2][lr] = av.z;
            As[lk + 3][lr] = av.w;
        }
        float4 bv = *(const float4*)&Bm[(size_t)(k0 + kr) * N + col0 + nc];
        *(float4*)&Bs[kr][nc] = bv;
        __syncthreads();

#pragma unroll
        for (int kk = 0; kk < BKg; kk++) {
            ulonglong2 b2 = *(const ulonglong2*)&Bs[kk][tx * 4];
#pragma unroll
            for (int r = 0; r < TM; r++) {
                float a = As[kk][ty * TM + r];
                unsigned long long ap = pack2(a, a);
                acc2[r][0] = fma2_(ap, b2.x, acc2[r][0]);
                acc2[r][1] = fma2_(ap, b2.y, acc2[r][1]);
            }
        }
        __syncthreads();
    }

#pragma unroll
    for (int r = 0; r < TM; r++) {
        float2 e0 = unpack2(acc2[r][0]);
        float2 e1 = unpack2(acc2[r][1]);
        float4 out = make_float4(e0.x, e0.y, e1.x, e1.y);
        *(float4*)&Cm[(size_t)(row0 + ty * TM + r) * N + col0 + tx * 4] = out;
    }
}

__global__ void proj_kernel(const float* __restrict__ x,
                            const float* __restrict__ W0,
                            const float* __restrict__ W1,
                            const float* __restrict__ W2)
{
    const int z = blockIdx.z;
    const float* W = (z == 0) ? W0 : ((z == 1) ? W1 : W2);
    gemm_body_t<4>(x, W, g_P + (size_t)z * BTC, B_ * T_, C_, C_);
}

__global__ void vproj_kernel(const float* __restrict__ Wv0,
                             const float* __restrict__ Wv1)
{
    const int z = blockIdx.z;
    gemm_body_t<2>(g_P + (size_t)(z + 1) * BTC, z ? Wv1 : Wv0,
                   g_V + (size_t)z * BTC, B_ * T_ * NH_, HS_, HS_);
}

__global__ void out_kernel(const float* __restrict__ Wc, float* __restrict__ out)
{
    gemm_body_t<2>(g_y, Wc, out, B_ * T_, C_, C_);
}

// ---------------------------------------------------------------------------
// s2[b,h,t] = sum_d p2[b,h,t,d]
// ---------------------------------------------------------------------------
__global__ void s2_kernel()
{
    const int warp = (blockIdx.x * blockDim.x + threadIdx.x) >> 5;
    const int lane = threadIdx.x & 31;
    if (warp >= B_ * T_ * NH_) return;
    const float* row = g_P + (size_t)2 * BTC + (size_t)warp * HS_;
    float v = row[lane] + row[lane + 32];
#pragma unroll
    for (int o = 16; o; o >>= 1) v += __shfl_down_sync(0xffffffffu, v, o);
    if (lane == 0) {
        const int b = warp / (T_ * NH_);
        const int t = (warp / NH_) % T_;
        const int h = warp % NH_;
        g_s2[(b * NH_ + h) * T_ + t] = v;
    }
}

// ---------------------------------------------------------------------------
// Higher-order attention via tf32 mma.sync:
//   block = (b,h,i), 256 threads = 8 warps. Warp s owns j-strip [16s, 16s+16).
//   A = W (exp weights, built per k-tile directly in tf32 fragments, masked),
//   B = V1 (tf32, smem, pad 72), D = U strip (fp32 regs).
//   y_d = (1/Z) sum_j V0[j,d] * U[j,d].
// ---------------------------------------------------------------------------
#define V1P 72   // padded smem stride (conflict-free B-frag LDS)

__global__ __launch_bounds__(256) void attn_kernel()
{
    const int i = T_ - 1 - blockIdx.x;   // big-i first (load balance)
    const int h = blockIdx.y;
    const int b = blockIdx.z;
    const int tid = threadIdx.x;
    const int lane = tid & 31;
    const int warp = tid >> 5;           // = j-strip index s

    __shared__ float s_v1[T_][V1P];      // V1 tf32-rounded, [k][d]
    __shared__ float s_ypart[8][64];     // per-warp y partials
    __shared__ float s_s2[T_];
    __shared__ float s_a[T_];            // pre-scaled: a * SCALE * log2e
    __shared__ float s_p0[HS_];
    __shared__ float s_red[256];
    __shared__ float s_red2[256];
    __shared__ float s_wred[8];
    __shared__ float s_m, s_zz;

    const size_t headoff = (size_t)(b * T_) * C_ + (size_t)h * HS_;
    const float* p0 = g_P + headoff + (size_t)i * C_;
    const float* p1 = g_P + BTC + headoff;
    const float* v0g = g_V + headoff;
    const float* v1g = g_V + BTC + headoff;
    const float* s2r = g_s2 + (b * NH_ + h) * T_;

    // ---- loads ----
    if (tid < 64) s_p0[tid] = p0[tid];
    if (tid < 128) s_s2[tid] = s2r[tid];
    // V1 -> smem, tf32-rounded (coalesced)
    for (int idx = tid; idx < T_ * 64; idx += 256) {
        const int k = idx >> 6;
        const int d = idx & 63;
        float v = __ldg(&v1g[(size_t)k * C_ + d]);
        s_v1[k][d] = __uint_as_float(tf32_(v));
    }
    // zero y partials
    s_ypart[warp][lane] = 0.f;
    s_ypart[warp][lane + 32] = 0.f;
    __syncthreads();

    // ---- a2[j] = SCALE*log2e * p0[i].p1[j], warp per j ----
    for (int j = warp; j <= i; j += 8) {
        const float* r = p1 + (size_t)j * C_;
        float v = fmaf(s_p0[lane], __ldg(&r[lane]),
                       s_p0[lane + 32] * __ldg(&r[lane + 32]));
#pragma unroll
        for (int o = 16; o; o >>= 1) v += __shfl_down_sync(0xffffffffu, v, o);
        if (lane == 0) s_a[j] = v * (SCALE_ * LOG2E_);
    }
    __syncthreads();

    // ---- prefix max/min of s2 (warp 0, shuffle scan) ----
    if (warp == 0) {
        float4 s4 = *(const float4*)&s_s2[lane << 2];
        float px1 = fmaxf(s4.x, s4.y), px2 = fmaxf(px1, s4.z), px3 = fmaxf(px2, s4.w);
        float pn1 = fminf(s4.x, s4.y), pn2 = fminf(pn1, s4.z), pn3 = fminf(pn2, s4.w);
        float im = px3, in_ = pn3;
#pragma unroll
        for (int off = 1; off < 32; off <<= 1) {
            float tm = __shfl_up_sync(0xffffffffu, im, off);
            float tn = __shfl_up_sync(0xffffffffu, in_, off);
            if (lane >= off) { im = fmaxf(im, tm); in_ = fminf(in_, tn); }
        }
        float em = __shfl_up_sync(0xffffffffu, im, 1);
        float en = __shfl_up_sync(0xffffffffu, in_, 1);
        if (lane == 0) { em = -3.4e38f; en = 3.4e38f; }
        s_red [(lane << 2) + 0] = fmaxf(em, s4.x);
        s_red [(lane << 2) + 1] = fmaxf(em, px1);
        s_red [(lane << 2) + 2] = fmaxf(em, px2);
        s_red [(lane << 2) + 3] = fmaxf(em, px3);
        s_red2[(lane << 2) + 0] = fminf(en, s4.x);
        s_red2[(lane << 2) + 1] = fminf(en, pn1);
        s_red2[(lane << 2) + 2] = fminf(en, pn2);
        s_red2[(lane << 2) + 3] = fminf(en, pn3);
    }
    __syncthreads();

    // exact max (log2 units) over valid triples
    float cand = -3.4e38f;
    if (tid <= i) {
        float aj = s_a[tid];
        cand = (aj >= 0.f) ? aj * s_red[tid] : aj * s_red2[tid];
    }
#pragma unroll
    for (int o = 16; o; o >>= 1)
        cand = fmaxf(cand, __shfl_down_sync(0xffffffffu, cand, o));
    if (lane == 0) s_wred[warp] = cand;
    __syncthreads();
    if (tid == 0) {
        float m = s_wred[0];
#pragma unroll
        for (int w = 1; w < 8; w++) m = fmaxf(m, s_wred[w]);
        s_m = m;
    }
    __syncthreads();
    const float negm2 = -s_m;

    float zpart = 0.f;

    // ---- per-warp strip MMA ----
    const int g = lane >> 2;             // 0..7
    const int t4 = lane & 3;             // 0..3
    const int jr0 = (warp << 4) + g;     // A rows this thread covers
    const int jr1 = jr0 + 8;

    if ((warp << 4) <= i) {
        const float a0s = s_a[jr0];      // garbage if jr0 > i (masked below)
        const float a1s = s_a[jr1];
        const bool rok0 = (jr0 <= i);
        const bool rok1 = (jr1 <= i);

        const int jmax = min((warp << 4) + 15, i);
        const int ktn = (jmax >> 3) + 1; // k-tiles needed

        float dacc[8][4];
#pragma unroll
        for (int nt = 0; nt < 8; nt++)
#pragma unroll
            for (int e = 0; e < 4; e++) dacc[nt][e] = 0.f;

        for (int kt = 0; kt < ktn; kt++) {
            const int kc0 = (kt << 3) + t4;
            const int kc1 = kc0 + 4;
            const float sk0 = s_s2[kc0];
            const float sk1 = s_s2[kc1];

            float e00 = ex2_(fmaf(a0s, sk0, negm2));
            float e10 = ex2_(fmaf(a1s, sk0, negm2));
            float e01 = ex2_(fmaf(a0s, sk1, negm2));
            float e11 = ex2_(fmaf(a1s, sk1, negm2));
            float w00 = (rok0 && kc0 <= jr0) ? e00 : 0.f;
            float w10 = (rok1 && kc0 <= jr1) ? e10 : 0.f;
            float w01 = (rok0 && kc1 <= jr0) ? e01 : 0.f;
            float w11 = (rok1 && kc1 <= jr1) ? e11 : 0.f;
            zpart += (w00 + w10) + (w01 + w11);

            const uint32_t au0 = tf32_(w00);
            const uint32_t au1 = tf32_(w10);
            const uint32_t au2 = tf32_(w01);
            const uint32_t au3 = tf32_(w11);

            const float* b0row = &s_v1[kc0][g];
            const float* b1row = &s_v1[kc1][g];
#pragma unroll
            for (int nt = 0; nt < 8; nt++) {
                uint32_t bu0 = __float_as_uint(b0row[nt << 3]);
                uint32_t bu1 = __float_as_uint(b1row[nt << 3]);
                asm volatile(
                    "mma.sync.aligned.m16n8k8.row.col.f32.tf32.tf32.f32 "
                    "{%0,%1,%2,%3}, {%4,%5,%6,%7}, {%8,%9}, {%0,%1,%2,%3};"
                    : "+f"(dacc[nt][0]), "+f"(dacc[nt][1]),
                      "+f"(dacc[nt][2]), "+f"(dacc[nt][3])
                    : "r"(au0), "r"(au1), "r"(au2), "r"(au3),
                      "r"(bu0), "r"(bu1));
            }
        }

        // ---- strip epilogue: y contribution, reduce over row-groups ----
#pragma unroll
        for (int nt = 0; nt < 8; nt++) {
            const int c0 = (nt << 3) + (t4 << 1);
            float2 va = *(const float2*)&v0g[(size_t)jr0 * C_ + c0];
            float2 vb = *(const float2*)&v0g[(size_t)jr1 * C_ + c0];
            float pc0 = fmaf(dacc[nt][0], va.x, dacc[nt][2] * vb.x);
            float pc1 = fmaf(dacc[nt][1], va.y, dacc[nt][3] * vb.y);
            // reduce over g (lanes stride 4)
            pc0 += __shfl_down_sync(0xffffffffu, pc0, 16);
            pc1 += __shfl_down_sync(0xffffffffu, pc1, 16);
            pc0 += __shfl_down_sync(0xffffffffu, pc0, 8);
            pc1 += __shfl_down_sync(0xffffffffu, pc1, 8);
            pc0 += __shfl_down_sync(0xffffffffu, pc0, 4);
            pc1 += __shfl_down_sync(0xffffffffu, pc1, 4);
            if (lane < 4) {
                s_ypart[warp][c0] = pc0;
                s_ypart[warp][c0 + 1] = pc1;
            }
        }
    }

    // ---- reductions: Z scalar, y over warps ----
    __syncthreads();
    s_red[tid] = zpart;
    __syncthreads();
    if (tid < 128) s_red[tid] += s_red[tid + 128];
    __syncthreads();
    if (tid < 64) s_red[tid] += s_red[tid + 64];
    __syncthreads();
    if (tid < 32) {
        float v = s_red[tid] + s_red[tid + 32];
#pragma unroll
        for (int o = 16; o; o >>= 1) v += __shfl_down_sync(0xffffffffu, v, o);
        if (tid == 0) s_zz = v;
    }
    __syncthreads();
    const float Z = s_zz;

    if (tid < 64) {
        float acc = 0.f;
#pragma unroll
        for (int w = 0; w < 8; w++) acc += s_ypart[w][tid];
        g_y[(size_t)(b * T_ + i) * C_ + (size_t)h * HS_ + tid] = acc / Z;
    }
}

// ---------------------------------------------------------------------------
extern "C" void kernel_launch(void* const* d_in, const int* in_sizes, int n_in,
                              void* d_out, int out_size)
{
    (void)in_sizes; (void)n_in; (void)out_size;
    const float* x   = (const float*)d_in[0];
    const float* Wp0 = (const float*)d_in[1];
    const float* Wp1 = (const float*)d_in[2];
    const float* Wp2 = (const float*)d_in[3];
    const float* Wv0 = (const float*)d_in[4];
    const float* Wv1 = (const float*)d_in[5];
    const float* Wc  = (const float*)d_in[6];
    float* out = (float*)d_out;

    proj_kernel<<<dim3(C_ / BNg, (B_ * T_) / 64, 3), 256>>>(x, Wp0, Wp1, Wp2);
    vproj_kernel<<<dim3(1, (B_ * T_ * NH_) / 32, 2), 256>>>(Wv0, Wv1);
    s2_kernel<<<(B_ * NH_ * T_ * 32 + 255) / 256, 256>>>();
    attn_kernel<<<dim3(T_, NH_, B_), 256>>>();
    out_kernel<<<dim3(C_ / BNg, (B_ * T_) / 32), 256>>>(Wc, out);
}

// round 6
// speedup vs baseline: 2.9741x; 1.1860x over previous
#include <cuda_runtime.h>
#include <stdint.h>

#define B_  4
#define T_  128
#define C_  512
#define NH_ 8
#define HS_ 64
#define BTC (B_*T_*C_)
#define SCALE_ 0.125f
#define LOG2E_ 1.4426950408889634f
#define IT_ 8    // i's per attn block (stride 16)

// Scratch (allocation-free rule: __device__ globals)
__device__ float g_P[3 * BTC];      // p0,p1,p2 in (B,T,C) layout
__device__ float g_V[2 * BTC];      // V0,V1 in (B,T,C) layout
__device__ float g_s2[B_ * NH_ * T_];
__device__ float g_y[BTC];          // (B,T,C) layout

// ---------------------------------------------------------------------------
// Packed fp32x2 + misc helpers
// ---------------------------------------------------------------------------
__device__ __forceinline__ unsigned long long pack2(float lo, float hi)
{
    unsigned long long r;
    asm("mov.b64 %0, {%1, %2};" : "=l"(r) : "f"(lo), "f"(hi));
    return r;
}
__device__ __forceinline__ unsigned long long fma2_(unsigned long long a,
                                                    unsigned long long b,
                                                    unsigned long long c)
{
    unsigned long long d;
    asm("fma.rn.f32x2 %0, %1, %2, %3;" : "=l"(d) : "l"(a), "l"(b), "l"(c));
    return d;
}
__device__ __forceinline__ float2 unpack2(unsigned long long v)
{
    float lo, hi;
    asm("mov.b64 {%0, %1}, %2;" : "=f"(lo), "=f"(hi) : "l"(v));
    return make_float2(lo, hi);
}
__device__ __forceinline__ float ex2_(float x)
{
    float r;
    asm("ex2.approx.f32 %0, %1;" : "=f"(r) : "f"(x));
    return r;
}
__device__ __forceinline__ uint32_t tf32_(float x)
{
    uint32_t r;
    asm("cvt.rna.tf32.f32 %0, %1;" : "=r"(r) : "f"(x));
    return r;
}

// ---------------------------------------------------------------------------
// Templated fp32 GEMM body: C[M,N] = A[M,K] @ B[K,N], row-major.
// ROWSUM: also emit per-row sums over the 64-col tile into g_s2
// (used for the p2 projection; col-block == head since HS==BNg==64).
// ---------------------------------------------------------------------------
#define BNg 64
#define BKg 16

template<int TM, bool ROWSUM>
__device__ __forceinline__ void gemm_body_t(
    const float* __restrict__ A, const float* __restrict__ Bm,
    float* __restrict__ Cm, int M, int N, int K)
{
    constexpr int BM = 16 * TM;
    __shared__ float As[BKg][BM];
    __shared__ float Bs[BKg][BNg];

    const int tid = threadIdx.x;
    const int tx = tid & 15;
    const int ty = tid >> 4;
    const int row0 = blockIdx.y * BM;
    const int col0 = blockIdx.x * BNg;

    const int kr = tid >> 4;
    const int nc = (tid & 15) * 4;

    unsigned long long acc2[TM][2];
#pragma unroll
    for (int r = 0; r < TM; r++) { acc2[r][0] = 0ull; acc2[r][1] = 0ull; }

    for (int k0 = 0; k0 < K; k0 += BKg) {
#pragma unroll
        for (int l = tid; l < BM * 4; l += 256) {
            const int lr = l >> 2;
            const int lk = (l & 3) << 2;
            float4 av = *(const float4*)&A[(size_t)(row0 + lr) * K + k0 + lk];
            As[lk + 0][lr] = av.x;
            As[lk + 1][lr] = av.y;
            As[lk + 2][lr] = av.z;
            As[lk + 3][lr] = av.w;
        }
        float4 bv = *(const float4*)&Bm[(size_t)(k0 + kr) * N + col0 + nc];
        *(float4*)&Bs[kr][nc] = bv;
        __syncthreads();

#pragma unroll
        for (int kk = 0; kk < BKg; kk++) {
            ulonglong2 b2 = *(const ulonglong2*)&Bs[kk][tx * 4];
#pragma unroll
            for (int r = 0; r < TM; r++) {
                float a = As[kk][ty * TM + r];
                unsigned long long ap = pack2(a, a);
                acc2[r][0] = fma2_(ap, b2.x, acc2[r][0]);
                acc2[r][1] = fma2_(ap, b2.y, acc2[r][1]);
            }
        }
        __syncthreads();
    }

#pragma unroll
    for (int r = 0; r < TM; r++) {
        float2 e0 = unpack2(acc2[r][0]);
        float2 e1 = unpack2(acc2[r][1]);
        float4 out = make_float4(e0.x, e0.y, e1.x, e1.y);
        *(float4*)&Cm[(size_t)(row0 + ty * TM + r) * N + col0 + tx * 4] = out;
    }

    if (ROWSUM) {
        // row sums of this 64x64 tile -> g_s2[(b*NH+h)*T + t], h = blockIdx.x
        float* s_rs = &As[0][0];          // reuse: 64 rows x 16 tx
        __syncthreads();
#pragma unroll
        for (int r = 0; r < TM; r++) {
            float2 e0 = unpack2(acc2[r][0]);
            float2 e1 = unpack2(acc2[r][1]);
            s_rs[(ty * TM + r) * 16 + tx] = (e0.x + e0.y) + (e1.x + e1.y);
        }
        __syncthreads();
        if (tid < BM) {
            float s = 0.f;
#pragma unroll
            for (int c = 0; c < 16; c++) s += s_rs[tid * 16 + c];
            const int grow = row0 + tid;          // global token row
            const int bb = grow / T_, tt = grow % T_;
            g_s2[(bb * NH_ + blockIdx.x) * T_ + tt] = s;
        }
    }
}

__global__ void proj_kernel(const float* __restrict__ x,
                            const float* __restrict__ W0,
                            const float* __restrict__ W1,
                            const float* __restrict__ W2)
{
    const int z = blockIdx.z;
    if (z == 2) {
        gemm_body_t<4, true>(x, W2, g_P + (size_t)2 * BTC, B_ * T_, C_, C_);
    } else {
        const float* W = (z == 0) ? W0 : W1;
        gemm_body_t<4, false>(x, W, g_P + (size_t)z * BTC, B_ * T_, C_, C_);
    }
}

__global__ void vproj_kernel(const float* __restrict__ Wv0,
                             const float* __restrict__ Wv1)
{
    const int z = blockIdx.z;
    gemm_body_t<2, false>(g_P + (size_t)(z + 1) * BTC, z ? Wv1 : Wv0,
                          g_V + (size_t)z * BTC, B_ * T_ * NH_, HS_, HS_);
}

__global__ void out_kernel(const float* __restrict__ Wc, float* __restrict__ out)
{
    gemm_body_t<2, false>(g_y, Wc, out, B_ * T_, C_, C_);
}

// ---------------------------------------------------------------------------
// Higher-order attention via tf32 mma.sync, i-batched:
//   block = (b, h, it), handles i = it + 16*l, l = 0..7 (balanced work).
//   8 warps = j-strips. No __syncthreads in the i/kt mainloop; per-i
//   combination via shared-memory atomicAdd (s_y, s_z).
// ---------------------------------------------------------------------------
#define V1P 72   // padded smem stride (conflict-free B-frag LDS)

__global__ __launch_bounds__(256, 4) void attn_kernel()
{
    const int it = blockIdx.x;           // 0..15 (i residue)
    const int h = blockIdx.y;
    const int b = blockIdx.z;
    const int tid = threadIdx.x;
    const int lane = tid & 31;
    const int warp = tid >> 5;

    __shared__ float s_v1[T_][V1P];      // V1 tf32-rounded [k][d]   36864 B
    __shared__ float s_a[IT_][T_];       // a2 per (l, j)             4096 B
    __shared__ float s_p0[IT_][HS_];     // p0 rows for the 8 i's     2048 B
    __shared__ float s_y[IT_][HS_];      // y accumulators            2048 B
    __shared__ float s_pmax[T_];         //                            512 B
    __shared__ float s_pmin[T_];         //                            512 B
    __shared__ float s_s2[T_];           //                            512 B
    __shared__ float s_m[IT_];
    __shared__ float s_z[IT_];

    const size_t headoff = (size_t)(b * T_) * C_ + (size_t)h * HS_;
    const float* p1 = g_P + BTC + headoff;
    const float* v0g = g_V + headoff;
    const float* v1g = g_V + BTC + headoff;
    const float* s2r = g_s2 + (b * NH_ + h) * T_;

    // ---- prologue loads (once per 8 i's) ----
    if (tid < 128) s_s2[tid] = s2r[tid];
    for (int idx = tid; idx < IT_ * HS_; idx += 256) {
        const int l = idx >> 6, d = idx & 63;
        const int i = it + (l << 4);
        s_p0[l][d] = __ldg(&g_P[headoff + (size_t)i * C_ + d]);
    }
    ((float*)s_y)[tid] = 0.f;
    ((float*)s_y)[tid + 256] = 0.f;
    if (tid < IT_) s_z[tid] = 0.f;
    // V1 -> smem, tf32-rounded (coalesced float4)
    for (int idx = tid; idx < T_ * 16; idx += 256) {
        const int k = idx >> 4;
        const int d4 = (idx & 15) << 2;
        float4 v = __ldg((const float4*)&v1g[(size_t)k * C_ + d4]);
        v.x = __uint_as_float(tf32_(v.x));
        v.y = __uint_as_float(tf32_(v.y));
        v.z = __uint_as_float(tf32_(v.z));
        v.w = __uint_as_float(tf32_(v.w));
        *(float4*)&s_v1[k][d4] = v;
    }
    __syncthreads();

    // ---- a2[l][j] = SCALE*log2e * p0[i_l].p1[j] ----
    {
        const int j = tid & 127;
        const int half = tid >> 7;
        const float* r = p1 + (size_t)j * C_;
        float dot0 = 0.f, dot1 = 0.f, dot2 = 0.f, dot3 = 0.f;
#pragma unroll
        for (int d = 0; d < 64; d += 4) {
            float4 rv = __ldg((const float4*)(r + d));
            float4 p0a = *(const float4*)&s_p0[half + 0][d];
            float4 p0b = *(const float4*)&s_p0[half + 2][d];
            float4 p0c = *(const float4*)&s_p0[half + 4][d];
            float4 p0d = *(const float4*)&s_p0[half + 6][d];
            dot0 = fmaf(p0a.x, rv.x, dot0); dot0 = fmaf(p0a.y, rv.y, dot0);
            dot0 = fmaf(p0a.z, rv.z, dot0); dot0 = fmaf(p0a.w, rv.w, dot0);
            dot1 = fmaf(p0b.x, rv.x, dot1); dot1 = fmaf(p0b.y, rv.y, dot1);
            dot1 = fmaf(p0b.z, rv.z, dot1); dot1 = fmaf(p0b.w, rv.w, dot1);
            dot2 = fmaf(p0c.x, rv.x, dot2); dot2 = fmaf(p0c.y, rv.y, dot2);
            dot2 = fmaf(p0c.z, rv.z, dot2); dot2 = fmaf(p0c.w, rv.w, dot2);
            dot3 = fmaf(p0d.x, rv.x, dot3); dot3 = fmaf(p0d.y, rv.y, dot3);
            dot3 = fmaf(p0d.z, rv.z, dot3); dot3 = fmaf(p0d.w, rv.w, dot3);
        }
        s_a[half + 0][j] = dot0 * (SCALE_ * LOG2E_);
        s_a[half + 2][j] = dot1 * (SCALE_ * LOG2E_);
        s_a[half + 4][j] = dot2 * (SCALE_ * LOG2E_);
        s_a[half + 6][j] = dot3 * (SCALE_ * LOG2E_);
    }
    __syncthreads();

    // ---- prefix max/min of s2 (warp 0, shuffle scan) ----
    if (warp == 0) {
        float4 s4 = *(const float4*)&s_s2[lane << 2];
        float px1 = fmaxf(s4.x, s4.y), px2 = fmaxf(px1, s4.z), px3 = fmaxf(px2, s4.w);
        float pn1 = fminf(s4.x, s4.y), pn2 = fminf(pn1, s4.z), pn3 = fminf(pn2, s4.w);
        float im = px3, in_ = pn3;
#pragma unroll
        for (int off = 1; off < 32; off <<= 1) {
            float tm = __shfl_up_sync(0xffffffffu, im, off);
            float tn = __shfl_up_sync(0xffffffffu, in_, off);
            if (lane >= off) { im = fmaxf(im, tm); in_ = fminf(in_, tn); }
        }
        float em = __shfl_up_sync(0xffffffffu, im, 1);
        float en = __shfl_up_sync(0xffffffffu, in_, 1);
        if (lane == 0) { em = -3.4e38f; en = 3.4e38f; }
        s_pmax[(lane << 2) + 0] = fmaxf(em, s4.x);
        s_pmax[(lane << 2) + 1] = fmaxf(em, px1);
        s_pmax[(lane << 2) + 2] = fmaxf(em, px2);
        s_pmax[(lane << 2) + 3] = fmaxf(em, px3);
        s_pmin[(lane << 2) + 0] = fminf(en, s4.x);
        s_pmin[(lane << 2) + 1] = fminf(en, pn1);
        s_pmin[(lane << 2) + 2] = fminf(en, pn2);
        s_pmin[(lane << 2) + 3] = fminf(en, pn3);
    }
    __syncthreads();

    // ---- exact max per i (warp l handles i_l) ----
    {
        const int i = it + (warp << 4);
        float m = -3.4e38f;
        for (int jj = lane; jj <= i; jj += 32) {
            float aj = s_a[warp][jj];
            float c = (aj >= 0.f) ? aj * s_pmax[jj] : aj * s_pmin[jj];
            m = fmaxf(m, c);
        }
#pragma unroll
        for (int o = 16; o; o >>= 1)
            m = fmaxf(m, __shfl_down_sync(0xffffffffu, m, o));
        if (lane == 0) s_m[warp] = m;
    }
    __syncthreads();

    // ---- mainloop over the 8 i's: NO block syncs inside ----
    const int g = lane >> 2;
    const int t4 = lane & 3;
    const int jr0 = (warp << 4) + g;
    const int jr1 = jr0 + 8;

    for (int l = 0; l < IT_; l++) {
        const int i = it + (l << 4);
        if ((warp << 4) > i) continue;

        const float negm2 = -s_m[l];
        const float a0s = s_a[l][jr0];
        const float a1s = s_a[l][jr1];
        const bool rok0 = (jr0 <= i);
        const bool rok1 = (jr1 <= i);
        const int jmax = min((warp << 4) + 15, i);
        const int ktn = (jmax >> 3) + 1;

        float dacc[8][4];
#pragma unroll
        for (int nt = 0; nt < 8; nt++)
#pragma unroll
            for (int e = 0; e < 4; e++) dacc[nt][e] = 0.f;
        float zp = 0.f;

        for (int kt = 0; kt < ktn; kt++) {
            const int kc0 = (kt << 3) + t4;
            const int kc1 = kc0 + 4;
            const float sk0 = s_s2[kc0];
            const float sk1 = s_s2[kc1];

            float e00 = ex2_(fmaf(a0s, sk0, negm2));
            float e10 = ex2_(fmaf(a1s, sk0, negm2));
            float e01 = ex2_(fmaf(a0s, sk1, negm2));
            float e11 = ex2_(fmaf(a1s, sk1, negm2));
            float w00 = (rok0 && kc0 <= jr0) ? e00 : 0.f;
            float w10 = (rok1 && kc0 <= jr1) ? e10 : 0.f;
            float w01 = (rok0 && kc1 <= jr0) ? e01 : 0.f;
            float w11 = (rok1 && kc1 <= jr1) ? e11 : 0.f;
            zp += (w00 + w10) + (w01 + w11);

            const uint32_t au0 = tf32_(w00);
            const uint32_t au1 = tf32_(w10);
            const uint32_t au2 = tf32_(w01);
            const uint32_t au3 = tf32_(w11);

            const float* b0row = &s_v1[kc0][g];
            const float* b1row = &s_v1[kc1][g];
#pragma unroll
            for (int nt = 0; nt < 8; nt++) {
                uint32_t bu0 = __float_as_uint(b0row[nt << 3]);
                uint32_t bu1 = __float_as_uint(b1row[nt << 3]);
                asm volatile(
                    "mma.sync.aligned.m16n8k8.row.col.f32.tf32.tf32.f32 "
                    "{%0,%1,%2,%3}, {%4,%5,%6,%7}, {%8,%9}, {%0,%1,%2,%3};"
                    : "+f"(dacc[nt][0]), "+f"(dacc[nt][1]),
                      "+f"(dacc[nt][2]), "+f"(dacc[nt][3])
                    : "r"(au0), "r"(au1), "r"(au2), "r"(au3),
                      "r"(bu0), "r"(bu1));
            }
        }

        // epilogue for this i: y contribution (atomic into s_y)
#pragma unroll
        for (int nt = 0; nt < 8; nt++) {
            const int c0 = (nt << 3) + (t4 << 1);
            float2 va = *(const float2*)&v0g[(size_t)jr0 * C_ + c0];
            float2 vb = *(const float2*)&v0g[(size_t)jr1 * C_ + c0];
            float pc0 = fmaf(dacc[nt][0], va.x, dacc[nt][2] * vb.x);
            float pc1 = fmaf(dacc[nt][1], va.y, dacc[nt][3] * vb.y);
            pc0 += __shfl_down_sync(0xffffffffu, pc0, 16);
            pc1 += __shfl_down_sync(0xffffffffu, pc1, 16);
            pc0 += __shfl_down_sync(0xffffffffu, pc0, 8);
            pc1 += __shfl_down_sync(0xffffffffu, pc1, 8);
            pc0 += __shfl_down_sync(0xffffffffu, pc0, 4);
            pc1 += __shfl_down_sync(0xffffffffu, pc1, 4);
            if (lane < 4) {
                atomicAdd(&s_y[l][c0], pc0);
                atomicAdd(&s_y[l][c0 + 1], pc1);
            }
        }
        // z contribution
#pragma unroll
        for (int o = 16; o; o >>= 1)
            zp += __shfl_down_sync(0xffffffffu, zp, o);
        if (lane == 0) atomicAdd(&s_z[l], zp);
    }

    __syncthreads();

    // ---- finalize ----
    for (int idx = tid; idx < IT_ * HS_; idx += 256) {
        const int l = idx >> 6, d = idx & 63;
        const int i = it + (l << 4);
        g_y[(size_t)(b * T_ + i) * C_ + (size_t)h * HS_ + d] = s_y[l][d] / s_z[l];
    }
}

// ---------------------------------------------------------------------------
extern "C" void kernel_launch(void* const* d_in, const int* in_sizes, int n_in,
                              void* d_out, int out_size)
{
    (void)in_sizes; (void)n_in; (void)out_size;
    const float* x   = (const float*)d_in[0];
    const float* Wp0 = (const float*)d_in[1];
    const float* Wp1 = (const float*)d_in[2];
    const float* Wp2 = (const float*)d_in[3];
    const float* Wv0 = (const float*)d_in[4];
    const float* Wv1 = (const float*)d_in[5];
    const float* Wc  = (const float*)d_in[6];
    float* out = (float*)d_out;

    proj_kernel<<<dim3(C_ / BNg, (B_ * T_) / 64, 3), 256>>>(x, Wp0, Wp1, Wp2);
    vproj_kernel<<<dim3(1, (B_ * T_ * NH_) / 32, 2), 256>>>(Wv0, Wv1);
    attn_kernel<<<dim3(T_ / IT_, NH_, B_), 256>>>();
    out_kernel<<<dim3(C_ / BNg, (B_ * T_) / 32), 256>>>(Wc, out);
}

// round 7
// speedup vs baseline: 2.9844x; 1.0034x over previous
#include <cuda_runtime.h>
#include <stdint.h>

#define B_  4
#define T_  128
#define C_  512
#define NH_ 8
#define HS_ 64
#define BTC (B_*T_*C_)
#define SCALE_ 0.125f
#define LOG2E_ 1.4426950408889634f
#define IT_ 8    // i's per attn block (stride 16)

// Scratch (allocation-free rule: __device__ globals)
__device__ float g_P[3 * BTC];      // p0,p1,p2 in (B,T,C) layout
__device__ float g_V[2 * BTC];      // V0,V1 in (B,T,C) layout
__device__ float g_s2[B_ * NH_ * T_];
__device__ float g_y[BTC];          // (B,T,C) layout

// ---------------------------------------------------------------------------
// Packed fp32x2 + misc helpers
// ---------------------------------------------------------------------------
__device__ __forceinline__ unsigned long long pack2(float lo, float hi)
{
    unsigned long long r;
    asm("mov.b64 %0, {%1, %2};" : "=l"(r) : "f"(lo), "f"(hi));
    return r;
}
__device__ __forceinline__ unsigned long long fma2_(unsigned long long a,
                                                    unsigned long long b,
                                                    unsigned long long c)
{
    unsigned long long d;
    asm("fma.rn.f32x2 %0, %1, %2, %3;" : "=l"(d) : "l"(a), "l"(b), "l"(c));
    return d;
}
__device__ __forceinline__ float2 unpack2(unsigned long long v)
{
    float lo, hi;
    asm("mov.b64 {%0, %1}, %2;" : "=f"(lo), "=f"(hi) : "l"(v));
    return make_float2(lo, hi);
}
__device__ __forceinline__ float ex2_(float x)
{
    float r;
    asm("ex2.approx.f32 %0, %1;" : "=f"(r) : "f"(x));
    return r;
}
__device__ __forceinline__ uint32_t tf32_(float x)
{
    uint32_t r;
    asm("cvt.rna.tf32.f32 %0, %1;" : "=r"(r) : "f"(x));
    return r;
}

// ---------------------------------------------------------------------------
// Double-buffered fp32 GEMM body: C[M,N] = A[M,K] @ B[K,N], row-major.
// Tile (16*TM) x 64, BK=16, 256 threads, register prefetch of next k-tile,
// ONE __syncthreads per k-iteration (writes target the non-read buffer).
// ROWSUM: also emit per-row sums over the 64-col tile into g_s2.
// ---------------------------------------------------------------------------
#define BNg 64
#define BKg 16

template<int TM, bool ROWSUM>
__device__ __forceinline__ void gemm_body_t(
    const float* __restrict__ A, const float* __restrict__ Bm,
    float* __restrict__ Cm, int M, int N, int K)
{
    constexpr int BM = 16 * TM;
    constexpr int NA = (BM * 4 + 255) / 256;   // A float4 loads per thread
    __shared__ float As[2][BKg][BM];
    __shared__ float Bs[2][BKg][BNg];

    const int tid = threadIdx.x;
    const int tx = tid & 15;
    const int ty = tid >> 4;
    const int row0 = blockIdx.y * BM;
    const int col0 = blockIdx.x * BNg;

    const int kr = tid >> 4;
    const int nc = (tid & 15) * 4;

    unsigned long long acc2[TM][2];
#pragma unroll
    for (int r = 0; r < TM; r++) { acc2[r][0] = 0ull; acc2[r][1] = 0ull; }

    const int nt = K / BKg;
    float4 avr[NA];
    float4 bvr;

    // preload tile 0 into registers
#pragma unroll
    for (int s = 0; s < NA; s++) {
        const int l = tid + (s << 8);
        if (l < BM * 4) {
            const int lr = l >> 2;
            const int lk = (l & 3) << 2;
            avr[s] = *(const float4*)&A[(size_t)(row0 + lr) * K + lk];
        }
    }
    bvr = *(const float4*)&Bm[(size_t)kr * N + col0 + nc];
    // store to buffer 0
#pragma unroll
    for (int s = 0; s < NA; s++) {
        const int l = tid + (s << 8);
        if (l < BM * 4) {
            const int lr = l >> 2;
            const int lk = (l & 3) << 2;
            As[0][lk + 0][lr] = avr[s].x;
            As[0][lk + 1][lr] = avr[s].y;
            As[0][lk + 2][lr] = avr[s].z;
            As[0][lk + 3][lr] = avr[s].w;
        }
    }
    *(float4*)&Bs[0][kr][nc] = bvr;
    __syncthreads();

    int cur = 0;
    for (int t = 0; t < nt; t++) {
        // prefetch next tile into registers (hidden behind compute)
        if (t + 1 < nt) {
            const int k0 = (t + 1) * BKg;
#pragma unroll
            for (int s = 0; s < NA; s++) {
                const int l = tid + (s << 8);
                if (l < BM * 4) {
                    const int lr = l >> 2;
                    const int lk = (l & 3) << 2;
                    avr[s] = *(const float4*)&A[(size_t)(row0 + lr) * K + k0 + lk];
                }
            }
            bvr = *(const float4*)&Bm[(size_t)(k0 + kr) * N + col0 + nc];
        }

        // compute on current buffer
#pragma unroll
        for (int kk = 0; kk < BKg; kk++) {
            ulonglong2 b2 = *(const ulonglong2*)&Bs[cur][kk][tx * 4];
#pragma unroll
            for (int r = 0; r < TM; r++) {
                float a = As[cur][kk][ty * TM + r];
                unsigned long long ap = pack2(a, a);
                acc2[r][0] = fma2_(ap, b2.x, acc2[r][0]);
                acc2[r][1] = fma2_(ap, b2.y, acc2[r][1]);
            }
        }

        // stage next tile into the other buffer
        if (t + 1 < nt) {
            const int nb = cur ^ 1;
#pragma unroll
            for (int s = 0; s < NA; s++) {
                const int l = tid + (s << 8);
                if (l < BM * 4) {
                    const int lr = l >> 2;
                    const int lk = (l & 3) << 2;
                    As[nb][lk + 0][lr] = avr[s].x;
                    As[nb][lk + 1][lr] = avr[s].y;
                    As[nb][lk + 2][lr] = avr[s].z;
                    As[nb][lk + 3][lr] = avr[s].w;
                }
            }
            *(float4*)&Bs[nb][kr][nc] = bvr;
            __syncthreads();
            cur = nb;
        }
    }

#pragma unroll
    for (int r = 0; r < TM; r++) {
        float2 e0 = unpack2(acc2[r][0]);
        float2 e1 = unpack2(acc2[r][1]);
        float4 out = make_float4(e0.x, e0.y, e1.x, e1.y);
        *(float4*)&Cm[(size_t)(row0 + ty * TM + r) * N + col0 + tx * 4] = out;
    }

    if (ROWSUM) {
        // row sums of this 64x64 tile -> g_s2[(b*NH+h)*T + t], h = blockIdx.x
        float* s_rs = &As[0][0][0];       // reuse: BM rows x 16 tx
        __syncthreads();
#pragma unroll
        for (int r = 0; r < TM; r++) {
            float2 e0 = unpack2(acc2[r][0]);
            float2 e1 = unpack2(acc2[r][1]);
            s_rs[(ty * TM + r) * 16 + tx] = (e0.x + e0.y) + (e1.x + e1.y);
        }
        __syncthreads();
        if (tid < BM) {
            float s = 0.f;
#pragma unroll
            for (int c = 0; c < 16; c++) s += s_rs[tid * 16 + c];
            const int grow = row0 + tid;
            const int bb = grow / T_, tt = grow % T_;
            g_s2[(bb * NH_ + blockIdx.x) * T_ + tt] = s;
        }
    }
}

__global__ void proj_kernel(const float* __restrict__ x,
                            const float* __restrict__ W0,
                            const float* __restrict__ W1,
                            const float* __restrict__ W2)
{
    const int z = blockIdx.z;
    if (z == 2) {
        gemm_body_t<4, true>(x, W2, g_P + (size_t)2 * BTC, B_ * T_, C_, C_);
    } else {
        const float* W = (z == 0) ? W0 : W1;
        gemm_body_t<4, false>(x, W, g_P + (size_t)z * BTC, B_ * T_, C_, C_);
    }
}

__global__ void vproj_kernel(const float* __restrict__ Wv0,
                             const float* __restrict__ Wv1)
{
    const int z = blockIdx.z;
    gemm_body_t<2, false>(g_P + (size_t)(z + 1) * BTC, z ? Wv1 : Wv0,
                          g_V + (size_t)z * BTC, B_ * T_ * NH_, HS_, HS_);
}

__global__ void out_kernel(const float* __restrict__ Wc, float* __restrict__ out)
{
    gemm_body_t<2, false>(g_y, Wc, out, B_ * T_, C_, C_);
}

// ---------------------------------------------------------------------------
// Higher-order attention via tf32 mma.sync, i-batched (unchanged from R6).
// ---------------------------------------------------------------------------
#define V1P 72   // padded smem stride (conflict-free B-frag LDS)

__global__ __launch_bounds__(256, 4) void attn_kernel()
{
    const int it = blockIdx.x;           // 0..15 (i residue)
    const int h = blockIdx.y;
    const int b = blockIdx.z;
    const int tid = threadIdx.x;
    const int lane = tid & 31;
    const int warp = tid >> 5;

    __shared__ float s_v1[T_][V1P];
    __shared__ float s_a[IT_][T_];
    __shared__ float s_p0[IT_][HS_];
    __shared__ float s_y[IT_][HS_];
    __shared__ float s_pmax[T_];
    __shared__ float s_pmin[T_];
    __shared__ float s_s2[T_];
    __shared__ float s_m[IT_];
    __shared__ float s_z[IT_];

    const size_t headoff = (size_t)(b * T_) * C_ + (size_t)h * HS_;
    const float* p1 = g_P + BTC + headoff;
    const float* v0g = g_V + headoff;
    const float* v1g = g_V + BTC + headoff;
    const float* s2r = g_s2 + (b * NH_ + h) * T_;

    // ---- prologue loads (once per 8 i's) ----
    if (tid < 128) s_s2[tid] = s2r[tid];
    for (int idx = tid; idx < IT_ * HS_; idx += 256) {
        const int l = idx >> 6, d = idx & 63;
        const int i = it + (l << 4);
        s_p0[l][d] = __ldg(&g_P[headoff + (size_t)i * C_ + d]);
    }
    ((float*)s_y)[tid] = 0.f;
    ((float*)s_y)[tid + 256] = 0.f;
    if (tid < IT_) s_z[tid] = 0.f;
    for (int idx = tid; idx < T_ * 16; idx += 256) {
        const int k = idx >> 4;
        const int d4 = (idx & 15) << 2;
        float4 v = __ldg((const float4*)&v1g[(size_t)k * C_ + d4]);
        v.x = __uint_as_float(tf32_(v.x));
        v.y = __uint_as_float(tf32_(v.y));
        v.z = __uint_as_float(tf32_(v.z));
        v.w = __uint_as_float(tf32_(v.w));
        *(float4*)&s_v1[k][d4] = v;
    }
    __syncthreads();

    // ---- a2[l][j] = SCALE*log2e * p0[i_l].p1[j] ----
    {
        const int j = tid & 127;
        const int half = tid >> 7;
        const float* r = p1 + (size_t)j * C_;
        float dot0 = 0.f, dot1 = 0.f, dot2 = 0.f, dot3 = 0.f;
#pragma unroll
        for (int d = 0; d < 64; d += 4) {
            float4 rv = __ldg((const float4*)(r + d));
            float4 p0a = *(const float4*)&s_p0[half + 0][d];
            float4 p0b = *(const float4*)&s_p0[half + 2][d];
            float4 p0c = *(const float4*)&s_p0[half + 4][d];
            float4 p0d = *(const float4*)&s_p0[half + 6][d];
            dot0 = fmaf(p0a.x, rv.x, dot0); dot0 = fmaf(p0a.y, rv.y, dot0);
            dot0 = fmaf(p0a.z, rv.z, dot0); dot0 = fmaf(p0a.w, rv.w, dot0);
            dot1 = fmaf(p0b.x, rv.x, dot1); dot1 = fmaf(p0b.y, rv.y, dot1);
            dot1 = fmaf(p0b.z, rv.z, dot1); dot1 = fmaf(p0b.w, rv.w, dot1);
            dot2 = fmaf(p0c.x, rv.x, dot2); dot2 = fmaf(p0c.y, rv.y, dot2);
            dot2 = fmaf(p0c.z, rv.z, dot2); dot2 = fmaf(p0c.w, rv.w, dot2);
            dot3 = fmaf(p0d.x, rv.x, dot3); dot3 = fmaf(p0d.y, rv.y, dot3);
            dot3 = fmaf(p0d.z, rv.z, dot3); dot3 = fmaf(p0d.w, rv.w, dot3);
        }
        s_a[half + 0][j] = dot0 * (SCALE_ * LOG2E_);
        s_a[half + 2][j] = dot1 * (SCALE_ * LOG2E_);
        s_a[half + 4][j] = dot2 * (SCALE_ * LOG2E_);
        s_a[half + 6][j] = dot3 * (SCALE_ * LOG2E_);
    }
    __syncthreads();

    // ---- prefix max/min of s2 (warp 0, shuffle scan) ----
    if (warp == 0) {
        float4 s4 = *(const float4*)&s_s2[lane << 2];
        float px1 = fmaxf(s4.x, s4.y), px2 = fmaxf(px1, s4.z), px3 = fmaxf(px2, s4.w);
        float pn1 = fminf(s4.x, s4.y), pn2 = fminf(pn1, s4.z), pn3 = fminf(pn2, s4.w);
        float im = px3, in_ = pn3;
#pragma unroll
        for (int off = 1; off < 32; off <<= 1) {
            float tm = __shfl_up_sync(0xffffffffu, im, off);
            float tn = __shfl_up_sync(0xffffffffu, in_, off);
            if (lane >= off) { im = fmaxf(im, tm); in_ = fminf(in_, tn); }
        }
        float em = __shfl_up_sync(0xffffffffu, im, 1);
        float en = __shfl_up_sync(0xffffffffu, in_, 1);
        if (lane == 0) { em = -3.4e38f; en = 3.4e38f; }
        s_pmax[(lane << 2) + 0] = fmaxf(em, s4.x);
        s_pmax[(lane << 2) + 1] = fmaxf(em, px1);
        s_pmax[(lane << 2) + 2] = fmaxf(em, px2);
        s_pmax[(lane << 2) + 3] = fmaxf(em, px3);
        s_pmin[(lane << 2) + 0] = fminf(en, s4.x);
        s_pmin[(lane << 2) + 1] = fminf(en, pn1);
        s_pmin[(lane << 2) + 2] = fminf(en, pn2);
        s_pmin[(lane << 2) + 3] = fminf(en, pn3);
    }
    __syncthreads();

    // ---- exact max per i (warp l handles i_l) ----
    {
        const int i = it + (warp << 4);
        float m = -3.4e38f;
        for (int jj = lane; jj <= i; jj += 32) {
            float aj = s_a[warp][jj];
            float c = (aj >= 0.f) ? aj * s_pmax[jj] : aj * s_pmin[jj];
            m = fmaxf(m, c);
        }
#pragma unroll
        for (int o = 16; o; o >>= 1)
            m = fmaxf(m, __shfl_down_sync(0xffffffffu, m, o));
        if (lane == 0) s_m[warp] = m;
    }
    __syncthreads();

    // ---- mainloop over the 8 i's: NO block syncs inside ----
    const int g = lane >> 2;
    const int t4 = lane & 3;
    const int jr0 = (warp << 4) + g;
    const int jr1 = jr0 + 8;

    for (int l = 0; l < IT_; l++) {
        const int i = it + (l << 4);
        if ((warp << 4) > i) continue;

        const float negm2 = -s_m[l];
        const float a0s = s_a[l][jr0];
        const float a1s = s_a[l][jr1];
        const bool rok0 = (jr0 <= i);
        const bool rok1 = (jr1 <= i);
        const int jmax = min((warp << 4) + 15, i);
        const int ktn = (jmax >> 3) + 1;

        float dacc[8][4];
#pragma unroll
        for (int nt = 0; nt < 8; nt++)
#pragma unroll
            for (int e = 0; e < 4; e++) dacc[nt][e] = 0.f;
        float zp = 0.f;

        for (int kt = 0; kt < ktn; kt++) {
            const int kc0 = (kt << 3) + t4;
            const int kc1 = kc0 + 4;
            const float sk0 = s_s2[kc0];
            const float sk1 = s_s2[kc1];

            float e00 = ex2_(fmaf(a0s, sk0, negm2));
            float e10 = ex2_(fmaf(a1s, sk0, negm2));
            float e01 = ex2_(fmaf(a0s, sk1, negm2));
            float e11 = ex2_(fmaf(a1s, sk1, negm2));
            float w00 = (rok0 && kc0 <= jr0) ? e00 : 0.f;
            float w10 = (rok1 && kc0 <= jr1) ? e10 : 0.f;
            float w01 = (rok0 && kc1 <= jr0) ? e01 : 0.f;
            float w11 = (rok1 && kc1 <= jr1) ? e11 : 0.f;
            zp += (w00 + w10) + (w01 + w11);

            const uint32_t au0 = tf32_(w00);
            const uint32_t au1 = tf32_(w10);
            const uint32_t au2 = tf32_(w01);
            const uint32_t au3 = tf32_(w11);

            const float* b0row = &s_v1[kc0][g];
            const float* b1row = &s_v1[kc1][g];
#pragma unroll
            for (int nt = 0; nt < 8; nt++) {
                uint32_t bu0 = __float_as_uint(b0row[nt << 3]);
                uint32_t bu1 = __float_as_uint(b1row[nt << 3]);
                asm volatile(
                    "mma.sync.aligned.m16n8k8.row.col.f32.tf32.tf32.f32 "
                    "{%0,%1,%2,%3}, {%4,%5,%6,%7}, {%8,%9}, {%0,%1,%2,%3};"
                    : "+f"(dacc[nt][0]), "+f"(dacc[nt][1]),
                      "+f"(dacc[nt][2]), "+f"(dacc[nt][3])
                    : "r"(au0), "r"(au1), "r"(au2), "r"(au3),
                      "r"(bu0), "r"(bu1));
            }
        }

        // epilogue for this i: y contribution (atomic into s_y)
#pragma unroll
        for (int nt = 0; nt < 8; nt++) {
            const int c0 = (nt << 3) + (t4 << 1);
            float2 va = *(const float2*)&v0g[(size_t)jr0 * C_ + c0];
            float2 vb = *(const float2*)&v0g[(size_t)jr1 * C_ + c0];
            float pc0 = fmaf(dacc[nt][0], va.x, dacc[nt][2] * vb.x);
            float pc1 = fmaf(dacc[nt][1], va.y, dacc[nt][3] * vb.y);
            pc0 += __shfl_down_sync(0xffffffffu, pc0, 16);
            pc1 += __shfl_down_sync(0xffffffffu, pc1, 16);
            pc0 += __shfl_down_sync(0xffffffffu, pc0, 8);
            pc1 += __shfl_down_sync(0xffffffffu, pc1, 8);
            pc0 += __shfl_down_sync(0xffffffffu, pc0, 4);
            pc1 += __shfl_down_sync(0xffffffffu, pc1, 4);
            if (lane < 4) {
                atomicAdd(&s_y[l][c0], pc0);
                atomicAdd(&s_y[l][c0 + 1], pc1);
            }
        }
#pragma unroll
        for (int o = 16; o; o >>= 1)
            zp += __shfl_down_sync(0xffffffffu, zp, o);
        if (lane == 0) atomicAdd(&s_z[l], zp);
    }

    __syncthreads();

    // ---- finalize ----
    for (int idx = tid; idx < IT_ * HS_; idx += 256) {
        const int l = idx >> 6, d = idx & 63;
        const int i = it + (l << 4);
        g_y[(size_t)(b * T_ + i) * C_ + (size_t)h * HS_ + d] = s_y[l][d] / s_z[l];
    }
}

// ---------------------------------------------------------------------------
extern "C" void kernel_launch(void* const* d_in, const int* in_sizes, int n_in,
                              void* d_out, int out_size)
{
    (void)in_sizes; (void)n_in; (void)out_size;
    const float* x   = (const float*)d_in[0];
    const float* Wp0 = (const float*)d_in[1];
    const float* Wp1 = (const float*)d_in[2];
    const float* Wp2 = (const float*)d_in[3];
    const float* Wv0 = (const float*)d_in[4];
    const float* Wv1 = (const float*)d_in[5];
    const float* Wc  = (const float*)d_in[6];
    float* out = (float*)d_out;

    proj_kernel<<<dim3(C_ / BNg, (B_ * T_) / 64, 3), 256>>>(x, Wp0, Wp1, Wp2);
    vproj_kernel<<<dim3(1, (B_ * T_ * NH_) / 32, 2), 256>>>(Wv0, Wv1);
    attn_kernel<<<dim3(T_ / IT_, NH_, B_), 256>>>();
    out_kernel<<<dim3(C_ / BNg, (B_ * T_) / 32), 256>>>(Wc, out);
}

// round 8
// speedup vs baseline: 3.5070x; 1.1751x over previous
#include <cuda_runtime.h>
#include <stdint.h>

#define B_  4
#define T_  128
#define C_  512
#define NH_ 8
#define HS_ 64
#define BTC (B_*T_*C_)
#define SCALE_ 0.125f
#define LOG2E_ 1.4426950408889634f
#define IT_ 8    // i's per attn block (stride 16)

// Scratch (allocation-free rule: __device__ globals)
__device__ float g_P[3 * BTC];      // p0,p1,p2 in (B,T,C) layout
__device__ float g_V[2 * BTC];      // V0,V1 in (B,T,C) layout
__device__ float g_s2[B_ * NH_ * T_];
__device__ float g_y[BTC];          // (B,T,C) layout

// ---------------------------------------------------------------------------
// helpers
// ---------------------------------------------------------------------------
__device__ __forceinline__ unsigned long long pack2(float lo, float hi)
{
    unsigned long long r;
    asm("mov.b64 %0, {%1, %2};" : "=l"(r) : "f"(lo), "f"(hi));
    return r;
}
__device__ __forceinline__ unsigned long long fma2_(unsigned long long a,
                                                    unsigned long long b,
                                                    unsigned long long c)
{
    unsigned long long d;
    asm("fma.rn.f32x2 %0, %1, %2, %3;" : "=l"(d) : "l"(a), "l"(b), "l"(c));
    return d;
}
__device__ __forceinline__ float2 unpack2(unsigned long long v)
{
    float lo, hi;
    asm("mov.b64 {%0, %1}, %2;" : "=f"(lo), "=f"(hi) : "l"(v));
    return make_float2(lo, hi);
}
__device__ __forceinline__ float ex2_(float x)
{
    float r;
    asm("ex2.approx.f32 %0, %1;" : "=f"(r) : "f"(x));
    return r;
}
__device__ __forceinline__ uint32_t tf32_(float x)
{
    uint32_t r;
    asm("cvt.rna.tf32.f32 %0, %1;" : "=r"(r) : "f"(x));
    return r;
}
__device__ __forceinline__ uint32_t smaddr(const void* p)
{
    return (uint32_t)__cvta_generic_to_shared(p);
}
#define CPA16(dst, src) \
    asm volatile("cp.async.cg.shared.global [%0], [%1], 16;" \
                 :: "r"(dst), "l"(src) : "memory")
#define CPA_COMMIT() asm volatile("cp.async.commit_group;" ::: "memory")
#define CPA_WAIT(n)  asm volatile("cp.async.wait_group %0;" :: "n"(n) : "memory")

// ---------------------------------------------------------------------------
// 4-stage cp.async pipelined fp32 GEMM: C[M,N] = A[M,K] @ B[K,N], row-major.
// Tile (16*TM) x 64, BK=16, 256 threads.
// Per iter: wait_group(2) -> sync -> compute(t) -> issue(t+3)+commit.
// ROWSUM: also emit per-row sums over the 64-col tile into g_s2.
// ---------------------------------------------------------------------------
#define BNg 64
#define BKg 16
#define STG_ 4

template<int TM, bool ROWSUM>
__device__ __forceinline__ void gemm_body_t(
    const float* __restrict__ A, const float* __restrict__ Bm,
    float* __restrict__ Cm, int M, int N, int K)
{
    constexpr int BM = 16 * TM;
    __shared__ float As[STG_][BM][BKg];   // [m][k] (cp.async row fragments)
    __shared__ float Bs[STG_][BKg][BNg];

    const int tid = threadIdx.x;
    const int tx = tid & 15;
    const int ty = tid >> 4;
    const int row0 = blockIdx.y * BM;
    const int col0 = blockIdx.x * BNg;

    // cp.async mappings (16B each)
    const int a_row = tid >> 2;          // 0..63 (BM=64) / 0..31 (BM=32 uses tid<128)
    const int a_k4 = (tid & 3) << 2;
    const int b_k = tid >> 4;
    const int b_n4 = (tid & 15) << 2;
    const bool do_a = (TM == 4) || (tid < BM * 4);

    const int nt = K / BKg;

    unsigned long long acc2[TM][2];
#pragma unroll
    for (int r = 0; r < TM; r++) { acc2[r][0] = 0ull; acc2[r][1] = 0ull; }

    // prologue: stages 0..STG_-2
#pragma unroll
    for (int t = 0; t < STG_ - 1; t++) {
        if (t < nt) {
            if (do_a)
                CPA16(smaddr(&As[t][a_row][a_k4]),
                      &A[(size_t)(row0 + a_row) * K + t * BKg + a_k4]);
            CPA16(smaddr(&Bs[t][b_k][b_n4]),
                  &Bm[(size_t)(t * BKg + b_k) * N + col0 + b_n4]);
        }
        CPA_COMMIT();
    }

    for (int t = 0; t < nt; t++) {
        CPA_WAIT(STG_ - 2);
        __syncthreads();
        const int st = t & (STG_ - 1);

#pragma unroll
        for (int kk = 0; kk < BKg; kk++) {
            ulonglong2 b2 = *(const ulonglong2*)&Bs[st][kk][tx * 4];
#pragma unroll
            for (int r = 0; r < TM; r++) {
                float a = As[st][ty * TM + r][kk];
                unsigned long long ap = pack2(a, a);
                acc2[r][0] = fma2_(ap, b2.x, acc2[r][0]);
                acc2[r][1] = fma2_(ap, b2.y, acc2[r][1]);
            }
        }

        // fetch stage t+STG_-1 (safe: all warps passed this iter's sync,
        // so compute on the target buffer (t-1)%STG_ has finished everywhere)
        const int tf = t + STG_ - 1;
        if (tf < nt) {
            const int sf = tf & (STG_ - 1);
            if (do_a)
                CPA16(smaddr(&As[sf][a_row][a_k4]),
                      &A[(size_t)(row0 + a_row) * K + tf * BKg + a_k4]);
            CPA16(smaddr(&Bs[sf][b_k][b_n4]),
                  &Bm[(size_t)(tf * BKg + b_k) * N + col0 + b_n4]);
        }
        CPA_COMMIT();
    }

#pragma unroll
    for (int r = 0; r < TM; r++) {
        float2 e0 = unpack2(acc2[r][0]);
        float2 e1 = unpack2(acc2[r][1]);
        float4 out = make_float4(e0.x, e0.y, e1.x, e1.y);
        *(float4*)&Cm[(size_t)(row0 + ty * TM + r) * N + col0 + tx * 4] = out;
    }

    if (ROWSUM) {
        // row sums of this 64x64 tile -> g_s2[(b*NH+h)*T + t], h = blockIdx.x
        float* s_rs = &As[0][0][0];       // reuse: BM rows x 16 tx
        __syncthreads();
#pragma unroll
        for (int r = 0; r < TM; r++) {
            float2 e0 = unpack2(acc2[r][0]);
            float2 e1 = unpack2(acc2[r][1]);
            s_rs[(ty * TM + r) * 16 + tx] = (e0.x + e0.y) + (e1.x + e1.y);
        }
        __syncthreads();
        if (tid < BM) {
            float s = 0.f;
#pragma unroll
            for (int c = 0; c < 16; c++) s += s_rs[tid * 16 + c];
            const int grow = row0 + tid;
            const int bb = grow / T_, tt = grow % T_;
            g_s2[(bb * NH_ + blockIdx.x) * T_ + tt] = s;
        }
    }
}

__global__ void proj_kernel(const float* __restrict__ x,
                            const float* __restrict__ W0,
                            const float* __restrict__ W1,
                            const float* __restrict__ W2)
{
    const int z = blockIdx.z;
    if (z == 2) {
        gemm_body_t<4, true>(x, W2, g_P + (size_t)2 * BTC, B_ * T_, C_, C_);
    } else {
        const float* W = (z == 0) ? W0 : W1;
        gemm_body_t<4, false>(x, W, g_P + (size_t)z * BTC, B_ * T_, C_, C_);
    }
}

__global__ void vproj_kernel(const float* __restrict__ Wv0,
                             const float* __restrict__ Wv1)
{
    const int z = blockIdx.z;
    gemm_body_t<2, false>(g_P + (size_t)(z + 1) * BTC, z ? Wv1 : Wv0,
                          g_V + (size_t)z * BTC, B_ * T_ * NH_, HS_, HS_);
}

__global__ void out_kernel(const float* __restrict__ Wc, float* __restrict__ out)
{
    gemm_body_t<2, false>(g_y, Wc, out, B_ * T_, C_, C_);
}

// ---------------------------------------------------------------------------
// Higher-order attention via tf32 mma.sync, i-batched (unchanged from R6/R7).
// ---------------------------------------------------------------------------
#define V1P 72   // padded smem stride (conflict-free B-frag LDS)

__global__ __launch_bounds__(256, 4) void attn_kernel()
{
    const int it = blockIdx.x;           // 0..15 (i residue)
    const int h = blockIdx.y;
    const int b = blockIdx.z;
    const int tid = threadIdx.x;
    const int lane = tid & 31;
    const int warp = tid >> 5;

    __shared__ float s_v1[T_][V1P];
    __shared__ float s_a[IT_][T_];
    __shared__ float s_p0[IT_][HS_];
    __shared__ float s_y[IT_][HS_];
    __shared__ float s_pmax[T_];
    __shared__ float s_pmin[T_];
    __shared__ float s_s2[T_];
    __shared__ float s_m[IT_];
    __shared__ float s_z[IT_];

    const size_t headoff = (size_t)(b * T_) * C_ + (size_t)h * HS_;
    const float* p1 = g_P + BTC + headoff;
    const float* v0g = g_V + headoff;
    const float* v1g = g_V + BTC + headoff;
    const float* s2r = g_s2 + (b * NH_ + h) * T_;

    // ---- prologue loads (once per 8 i's) ----
    if (tid < 128) s_s2[tid] = s2r[tid];
    for (int idx = tid; idx < IT_ * HS_; idx += 256) {
        const int l = idx >> 6, d = idx & 63;
        const int i = it + (l << 4);
        s_p0[l][d] = __ldg(&g_P[headoff + (size_t)i * C_ + d]);
    }
    ((float*)s_y)[tid] = 0.f;
    ((float*)s_y)[tid + 256] = 0.f;
    if (tid < IT_) s_z[tid] = 0.f;
    for (int idx = tid; idx < T_ * 16; idx += 256) {
        const int k = idx >> 4;
        const int d4 = (idx & 15) << 2;
        float4 v = __ldg((const float4*)&v1g[(size_t)k * C_ + d4]);
        v.x = __uint_as_float(tf32_(v.x));
        v.y = __uint_as_float(tf32_(v.y));
        v.z = __uint_as_float(tf32_(v.z));
        v.w = __uint_as_float(tf32_(v.w));
        *(float4*)&s_v1[k][d4] = v;
    }
    __syncthreads();

    // ---- a2[l][j] = SCALE*log2e * p0[i_l].p1[j] ----
    {
        const int j = tid & 127;
        const int half = tid >> 7;
        const float* r = p1 + (size_t)j * C_;
        float dot0 = 0.f, dot1 = 0.f, dot2 = 0.f, dot3 = 0.f;
#pragma unroll
        for (int d = 0; d < 64; d += 4) {
            float4 rv = __ldg((const float4*)(r + d));
            float4 p0a = *(const float4*)&s_p0[half + 0][d];
            float4 p0b = *(const float4*)&s_p0[half + 2][d];
            float4 p0c = *(const float4*)&s_p0[half + 4][d];
            float4 p0d = *(const float4*)&s_p0[half + 6][d];
            dot0 = fmaf(p0a.x, rv.x, dot0); dot0 = fmaf(p0a.y, rv.y, dot0);
            dot0 = fmaf(p0a.z, rv.z, dot0); dot0 = fmaf(p0a.w, rv.w, dot0);
            dot1 = fmaf(p0b.x, rv.x, dot1); dot1 = fmaf(p0b.y, rv.y, dot1);
            dot1 = fmaf(p0b.z, rv.z, dot1); dot1 = fmaf(p0b.w, rv.w, dot1);
            dot2 = fmaf(p0c.x, rv.x, dot2); dot2 = fmaf(p0c.y, rv.y, dot2);
            dot2 = fmaf(p0c.z, rv.z, dot2); dot2 = fmaf(p0c.w, rv.w, dot2);
            dot3 = fmaf(p0d.x, rv.x, dot3); dot3 = fmaf(p0d.y, rv.y, dot3);
            dot3 = fmaf(p0d.z, rv.z, dot3); dot3 = fmaf(p0d.w, rv.w, dot3);
        }
        s_a[half + 0][j] = dot0 * (SCALE_ * LOG2E_);
        s_a[half + 2][j] = dot1 * (SCALE_ * LOG2E_);
        s_a[half + 4][j] = dot2 * (SCALE_ * LOG2E_);
        s_a[half + 6][j] = dot3 * (SCALE_ * LOG2E_);
    }
    __syncthreads();

    // ---- prefix max/min of s2 (warp 0, shuffle scan) ----
    if (warp == 0) {
        float4 s4 = *(const float4*)&s_s2[lane << 2];
        float px1 = fmaxf(s4.x, s4.y), px2 = fmaxf(px1, s4.z), px3 = fmaxf(px2, s4.w);
        float pn1 = fminf(s4.x, s4.y), pn2 = fminf(pn1, s4.z), pn3 = fminf(pn2, s4.w);
        float im = px3, in_ = pn3;
#pragma unroll
        for (int off = 1; off < 32; off <<= 1) {
            float tm = __shfl_up_sync(0xffffffffu, im, off);
            float tn = __shfl_up_sync(0xffffffffu, in_, off);
            if (lane >= off) { im = fmaxf(im, tm); in_ = fminf(in_, tn); }
        }
        float em = __shfl_up_sync(0xffffffffu, im, 1);
        float en = __shfl_up_sync(0xffffffffu, in_, 1);
        if (lane == 0) { em = -3.4e38f; en = 3.4e38f; }
        s_pmax[(lane << 2) + 0] = fmaxf(em, s4.x);
        s_pmax[(lane << 2) + 1] = fmaxf(em, px1);
        s_pmax[(lane << 2) + 2] = fmaxf(em, px2);
        s_pmax[(lane << 2) + 3] = fmaxf(em, px3);
        s_pmin[(lane << 2) + 0] = fminf(en, s4.x);
        s_pmin[(lane << 2) + 1] = fminf(en, pn1);
        s_pmin[(lane << 2) + 2] = fminf(en, pn2);
        s_pmin[(lane << 2) + 3] = fminf(en, pn3);
    }
    __syncthreads();

    // ---- exact max per i (warp l handles i_l) ----
    {
        const int i = it + (warp << 4);
        float m = -3.4e38f;
        for (int jj = lane; jj <= i; jj += 32) {
            float aj = s_a[warp][jj];
            float c = (aj >= 0.f) ? aj * s_pmax[jj] : aj * s_pmin[jj];
            m = fmaxf(m, c);
        }
#pragma unroll
        for (int o = 16; o; o >>= 1)
            m = fmaxf(m, __shfl_down_sync(0xffffffffu, m, o));
        if (lane == 0) s_m[warp] = m;
    }
    __syncthreads();

    // ---- mainloop over the 8 i's: NO block syncs inside ----
    const int g = lane >> 2;
    const int t4 = lane & 3;
    const int jr0 = (warp << 4) + g;
    const int jr1 = jr0 + 8;

    for (int l = 0; l < IT_; l++) {
        const int i = it + (l << 4);
        if ((warp << 4) > i) continue;

        const float negm2 = -s_m[l];
        const float a0s = s_a[l][jr0];
        const float a1s = s_a[l][jr1];
        const bool rok0 = (jr0 <= i);
        const bool rok1 = (jr1 <= i);
        const int jmax = min((warp << 4) + 15, i);
        const int ktn = (jmax >> 3) + 1;

        float dacc[8][4];
#pragma unroll
        for (int nt = 0; nt < 8; nt++)
#pragma unroll
            for (int e = 0; e < 4; e++) dacc[nt][e] = 0.f;
        float zp = 0.f;

        for (int kt = 0; kt < ktn; kt++) {
            const int kc0 = (kt << 3) + t4;
            const int kc1 = kc0 + 4;
            const float sk0 = s_s2[kc0];
            const float sk1 = s_s2[kc1];

            float e00 = ex2_(fmaf(a0s, sk0, negm2));
            float e10 = ex2_(fmaf(a1s, sk0, negm2));
            float e01 = ex2_(fmaf(a0s, sk1, negm2));
            float e11 = ex2_(fmaf(a1s, sk1, negm2));
            float w00 = (rok0 && kc0 <= jr0) ? e00 : 0.f;
            float w10 = (rok1 && kc0 <= jr1) ? e10 : 0.f;
            float w01 = (rok0 && kc1 <= jr0) ? e01 : 0.f;
            float w11 = (rok1 && kc1 <= jr1) ? e11 : 0.f;
            zp += (w00 + w10) + (w01 + w11);

            const uint32_t au0 = tf32_(w00);
            const uint32_t au1 = tf32_(w10);
            const uint32_t au2 = tf32_(w01);
            const uint32_t au3 = tf32_(w11);

            const float* b0row = &s_v1[kc0][g];
            const float* b1row = &s_v1[kc1][g];
#pragma unroll
            for (int nt = 0; nt < 8; nt++) {
                uint32_t bu0 = __float_as_uint(b0row[nt << 3]);
                uint32_t bu1 = __float_as_uint(b1row[nt << 3]);
                asm volatile(
                    "mma.sync.aligned.m16n8k8.row.col.f32.tf32.tf32.f32 "
                    "{%0,%1,%2,%3}, {%4,%5,%6,%7}, {%8,%9}, {%0,%1,%2,%3};"
                    : "+f"(dacc[nt][0]), "+f"(dacc[nt][1]),
                      "+f"(dacc[nt][2]), "+f"(dacc[nt][3])
                    : "r"(au0), "r"(au1), "r"(au2), "r"(au3),
                      "r"(bu0), "r"(bu1));
            }
        }

        // epilogue for this i: y contribution (atomic into s_y)
#pragma unroll
        for (int nt = 0; nt < 8; nt++) {
            const int c0 = (nt << 3) + (t4 << 1);
            float2 va = *(const float2*)&v0g[(size_t)jr0 * C_ + c0];
            float2 vb = *(const float2*)&v0g[(size_t)jr1 * C_ + c0];
            float pc0 = fmaf(dacc[nt][0], va.x, dacc[nt][2] * vb.x);
            float pc1 = fmaf(dacc[nt][1], va.y, dacc[nt][3] * vb.y);
            pc0 += __shfl_down_sync(0xffffffffu, pc0, 16);
            pc1 += __shfl_down_sync(0xffffffffu, pc1, 16);
            pc0 += __shfl_down_sync(0xffffffffu, pc0, 8);
            pc1 += __shfl_down_sync(0xffffffffu, pc1, 8);
            pc0 += __shfl_down_sync(0xffffffffu, pc0, 4);
            pc1 += __shfl_down_sync(0xffffffffu, pc1, 4);
            if (lane < 4) {
                atomicAdd(&s_y[l][c0], pc0);
                atomicAdd(&s_y[l][c0 + 1], pc1);
            }
        }
#pragma unroll
        for (int o = 16; o; o >>= 1)
            zp += __shfl_down_sync(0xffffffffu, zp, o);
        if (lane == 0) atomicAdd(&s_z[l], zp);
    }

    __syncthreads();

    // ---- finalize ----
    for (int idx = tid; idx < IT_ * HS_; idx += 256) {
        const int l = idx >> 6, d = idx & 63;
        const int i = it + (l << 4);
        g_y[(size_t)(b * T_ + i) * C_ + (size_t)h * HS_ + d] = s_y[l][d] / s_z[l];
    }
}

// ---------------------------------------------------------------------------
extern "C" void kernel_launch(void* const* d_in, const int* in_sizes, int n_in,
                              void* d_out, int out_size)
{
    (void)in_sizes; (void)n_in; (void)out_size;
    const float* x   = (const float*)d_in[0];
    const float* Wp0 = (const float*)d_in[1];
    const float* Wp1 = (const float*)d_in[2];
    const float* Wp2 = (const float*)d_in[3];
    const float* Wv0 = (const float*)d_in[4];
    const float* Wv1 = (const float*)d_in[5];
    const float* Wc  = (const float*)d_in[6];
    float* out = (float*)d_out;

    proj_kernel<<<dim3(C_ / BNg, (B_ * T_) / 64, 3), 256>>>(x, Wp0, Wp1, Wp2);
    vproj_kernel<<<dim3(1, (B_ * T_ * NH_) / 32, 2), 256>>>(Wv0, Wv1);
    attn_kernel<<<dim3(T_ / IT_, NH_, B_), 256>>>();
    out_kernel<<<dim3(C_ / BNg, (B_ * T_) / 32), 256>>>(Wc, out);
}